// round 10
// baseline (speedup 1.0000x reference)
#include <cuda_runtime.h>
#include <cuda_bf16.h>
#include <cstdint>

// Problem dims
#define B_SZ 64
#define T_SZ 512
#define D_SZ 1024
#define R_SZ 1024
#define O_SZ 1024
#define M_SZ (B_SZ * T_SZ)   // 32768

// ---------------- device scratch (static: no runtime allocation) ----------------
__device__ float          g_xh[(size_t)T_SZ * B_SZ * R_SZ];   // [T][B][R]
__device__ float          g_xz[(size_t)T_SZ * B_SZ * R_SZ];   // [T][B][R]
__device__ float          g_Mz[(size_t)R_SZ * R_SZ];          // Wxz @ Whz
__device__ unsigned short g_x_hi[(size_t)M_SZ * D_SZ];        // X bf16 hi
__device__ unsigned short g_x_lo[(size_t)M_SZ * D_SZ];        // X bf16 lo
__device__ unsigned short g_w_hi[(size_t)2048 * D_SZ];        // [Wxh;Wxz] bf16 hi
__device__ unsigned short g_w_lo[(size_t)2048 * D_SZ];        // [Wxh;Wxz] bf16 lo
__device__ unsigned short g_h_hi[2][B_SZ * R_SZ];             // h bf16 hi (dbl buf)
__device__ unsigned short g_h_lo[2][B_SZ * R_SZ];             // h bf16 lo
__device__ float          g_hf[B_SZ * R_SZ];                  // final h fp32
__device__ unsigned       g_flags[64];                        // per-CTA arrival flags
__device__ unsigned       g_release;                          // barrier release word

// ==================== helpers ====================
__device__ __forceinline__ uint32_t smem_u32(const void* p) {
    uint32_t a;
    asm("{ .reg .u64 t; cvta.to.shared.u64 t, %1; cvt.u32.u64 %0, t; }" : "=r"(a) : "l"(p));
    return a;
}
__device__ __forceinline__ void ldsm_x4(uint32_t r[4], uint32_t addr) {
    asm volatile("ldmatrix.sync.aligned.m8n8.x4.shared.b16 {%0,%1,%2,%3}, [%4];"
                 : "=r"(r[0]), "=r"(r[1]), "=r"(r[2]), "=r"(r[3]) : "r"(addr));
}
__device__ __forceinline__ void mma_bf16(float d[4], const uint32_t a[4],
                                         uint32_t b0, uint32_t b1) {
    asm volatile("mma.sync.aligned.m16n8k16.row.col.f32.bf16.bf16.f32 "
                 "{%0,%1,%2,%3}, {%4,%5,%6,%7}, {%8,%9}, {%0,%1,%2,%3};"
                 : "+f"(d[0]), "+f"(d[1]), "+f"(d[2]), "+f"(d[3])
                 : "r"(a[0]), "r"(a[1]), "r"(a[2]), "r"(a[3]), "r"(b0), "r"(b1));
}
__device__ __forceinline__ void cp_async16(uint32_t dst, const void* src) {
    asm volatile("cp.async.cg.shared.global [%0], [%1], 16;" :: "r"(dst), "l"(src));
}
#define CP_COMMIT() asm volatile("cp.async.commit_group;" ::: "memory")
#define CP_WAIT0()  asm volatile("cp.async.wait_group 0;" ::: "memory")
#define CP_WAIT1()  asm volatile("cp.async.wait_group 1;" ::: "memory")
#define BAR_SYNC(id, cnt) asm volatile("bar.sync %0, %1;" :: "r"(id), "r"(cnt) : "memory")

__device__ __forceinline__ uint32_t pack2_hi(float a, float b) {
    return (uint32_t)__bfloat16_as_ushort(__float2bfloat16_rn(a))
         | ((uint32_t)__bfloat16_as_ushort(__float2bfloat16_rn(b)) << 16);
}
__device__ __forceinline__ uint32_t pack2_lo(float a, float b) {
    float ra = a - __bfloat162float(__float2bfloat16_rn(a));
    float rb = b - __bfloat162float(__float2bfloat16_rn(b));
    return pack2_hi(ra, rb);
}

// ==================== init ====================
__global__ void init_kernel() {
    int i = blockIdx.x * blockDim.x + threadIdx.x;
    if (i < B_SZ * R_SZ) { g_h_hi[0][i] = 0; g_h_lo[0][i] = 0; }
    if (i < 64) g_flags[i] = 0u;
    if (i == 0) g_release = 0u;
}

// ==================== fp32 -> bf16 hi/lo split ====================
__global__ void __launch_bounds__(256) split_kernel(const float* __restrict__ src,
                                                    unsigned short* __restrict__ hi,
                                                    unsigned short* __restrict__ lo) {
    size_t i = ((size_t)blockIdx.x * 256 + threadIdx.x) * 4;
    float4 v = *(const float4*)(src + i);
    uint2 h, l;
    h.x = pack2_hi(v.x, v.y); h.y = pack2_hi(v.z, v.w);
    l.x = pack2_lo(v.x, v.y); l.y = pack2_lo(v.z, v.w);
    *(uint2*)(hi + i) = h;
    *(uint2*)(lo + i) = l;
}

// ==================== Mz = Wxz @ Whz (SIMT fp32) ====================
__global__ void __launch_bounds__(256) mz_kernel(const float* __restrict__ Wxz,
                                                 const float* __restrict__ Whz) {
    __shared__ float As[16][68];
    __shared__ float Bs[16][68];
    const int tid = threadIdx.x;
    const int i0 = blockIdx.x * 64;
    const int j0 = blockIdx.y * 64;
    const int tx = tid & 15;
    const int ty = tid >> 4;
    float acc[4][4] = {};

    for (int k0 = 0; k0 < R_SZ; k0 += 16) {
        {
            int row = tid >> 2;
            int c4  = (tid & 3) * 4;
            float4 a = *(const float4*)(Wxz + (size_t)(i0 + row) * R_SZ + k0 + c4);
            As[c4 + 0][row] = a.x; As[c4 + 1][row] = a.y;
            As[c4 + 2][row] = a.z; As[c4 + 3][row] = a.w;
        }
        {
            int kk = tid >> 4;
            int j4 = (tid & 15) * 4;
            float4 b = *(const float4*)(Whz + (size_t)(k0 + kk) * R_SZ + j0 + j4);
            *(float4*)&Bs[kk][j4] = b;
        }
        __syncthreads();
        #pragma unroll
        for (int kk = 0; kk < 16; kk++) {
            float ar[4], br[4];
            *(float4*)ar = *(const float4*)&As[kk][ty * 4];
            *(float4*)br = *(const float4*)&Bs[kk][tx * 4];
            #pragma unroll
            for (int i = 0; i < 4; i++)
                #pragma unroll
                for (int j = 0; j < 4; j++)
                    acc[i][j] = fmaf(ar[i], br[j], acc[i][j]);
        }
        __syncthreads();
    }
    #pragma unroll
    for (int i = 0; i < 4; i++) {
        float4 v = make_float4(acc[i][0], acc[i][1], acc[i][2], acc[i][3]);
        *(float4*)(g_Mz + (size_t)(i0 + ty * 4 + i) * R_SZ + j0 + tx * 4) = v;
    }
}

// ==================== Precompute xh/xz with HMMA + cp.async ====================
// 128x128 tile, BK=32, 512 threads (16 warps = 4m x 4n), warp tile 32x32.
#define PP_ROW_B 80
#define PP_PLANE 10240
#define PP_SMEM (8 * PP_PLANE)

__global__ void __launch_bounds__(512, 1) precompute_mma(const float* __restrict__ bh,
                                                         const float* __restrict__ bz) {
    extern __shared__ char psm[];
    const uint32_t sb = smem_u32(psm);
    const int tid = threadIdx.x, warp = tid >> 5, lane = tid & 31;
    const long m_blk = (long)blockIdx.y * 128;
    const int  n_blk = blockIdx.x * 128;

    const float* bias; float* dst; int rb;
    if (n_blk < R_SZ) { bias = bh; dst = g_xh; rb = n_blk; }
    else              { bias = bz; dst = g_xz; rb = n_blk - R_SZ; }

    const int m0w = (warp & 3) * 32;
    const int n0w = (warp >> 2) * 32;

    float acc[2][4][4];
    #pragma unroll
    for (int a = 0; a < 2; a++)
        #pragma unroll
        for (int b = 0; b < 4; b++)
            #pragma unroll
            for (int c = 0; c < 4; c++) acc[a][b][c] = 0.0f;

    auto stage = [&](int buf, int k0) {
        int row = tid >> 2;
        int qt  = tid & 3;
        size_t sa = (size_t)(m_blk + row) * D_SZ + k0 + qt * 8;
        size_t sw = (size_t)(n_blk + row) * D_SZ + k0 + qt * 8;
        uint32_t o = (uint32_t)row * PP_ROW_B + (uint32_t)qt * 16;
        uint32_t base = sb + (uint32_t)(buf * 4) * PP_PLANE;
        cp_async16(base + o,                 g_x_hi + sa);
        cp_async16(base + PP_PLANE + o,      g_x_lo + sa);
        cp_async16(base + 2 * PP_PLANE + o,  g_w_hi + sw);
        cp_async16(base + 3 * PP_PLANE + o,  g_w_lo + sw);
    };

    int buf = 0;
    stage(0, 0);
    CP_COMMIT();
    for (int s = 0; s < D_SZ / 32; s++) {
        if (s + 1 < D_SZ / 32) { stage(buf ^ 1, (s + 1) * 32); CP_COMMIT(); CP_WAIT1(); }
        else                   { CP_WAIT0(); }
        __syncthreads();

        const uint32_t AhS = sb + (uint32_t)((buf * 4 + 0) * PP_PLANE);
        const uint32_t AlS = AhS + PP_PLANE;
        const char* Bh = psm + (buf * 4 + 2) * PP_PLANE;
        const char* Bl = Bh + PP_PLANE;
        #pragma unroll
        for (int k16 = 0; k16 < 2; k16++) {
            uint32_t ahi[2][4], alo[2][4];
            #pragma unroll
            for (int mi = 0; mi < 2; mi++) {
                uint32_t ar = (uint32_t)(m0w + mi * 16 + (lane & 15)) * PP_ROW_B
                            + (uint32_t)(lane >> 4) * 16 + (uint32_t)k16 * 32;
                ldsm_x4(ahi[mi], AhS + ar);
                ldsm_x4(alo[mi], AlS + ar);
            }
            uint32_t bhw[4][2], blw[4][2];
            #pragma unroll
            for (int ni = 0; ni < 4; ni++) {
                uint32_t bo = (uint32_t)(n0w + ni * 8 + (lane >> 2)) * PP_ROW_B
                            + (uint32_t)((lane & 3) * 2) * 2 + (uint32_t)k16 * 32;
                bhw[ni][0] = *(const uint32_t*)(Bh + bo);
                bhw[ni][1] = *(const uint32_t*)(Bh + bo + 16);
                blw[ni][0] = *(const uint32_t*)(Bl + bo);
                blw[ni][1] = *(const uint32_t*)(Bl + bo + 16);
            }
            #pragma unroll
            for (int mi = 0; mi < 2; mi++)
                #pragma unroll
                for (int ni = 0; ni < 4; ni++) {
                    mma_bf16(acc[mi][ni], ahi[mi], bhw[ni][0], bhw[ni][1]);
                    mma_bf16(acc[mi][ni], ahi[mi], blw[ni][0], blw[ni][1]);
                    mma_bf16(acc[mi][ni], alo[mi], bhw[ni][0], bhw[ni][1]);
                }
        }
        __syncthreads();
        buf ^= 1;
    }

    #pragma unroll
    for (int ni = 0; ni < 4; ni++) {
        int col = n0w + ni * 8 + (lane & 3) * 2;
        float2 bv = *(const float2*)(bias + rb + col);
        #pragma unroll
        for (int mi = 0; mi < 2; mi++) {
            #pragma unroll
            for (int half = 0; half < 2; half++) {
                long m = m_blk + m0w + mi * 16 + (lane >> 2) + half * 8;
                int b = (int)(m >> 9), t = (int)(m & 511);
                float2 v;
                v.x = acc[mi][ni][half * 2 + 0] + bv.x;
                v.y = acc[mi][ni][half * 2 + 1] + bv.y;
                *(float2*)(dst + ((long)t * B_SZ + b) * R_SZ + rb + col) = v;
            }
        }
    }
}

// ==================== Persistent warp-MMA scan (16 warps, 4 groups, ldmatrix B) ====================
#define NCTA 64
#define KC 128
#define NCHUNK (R_SZ / KC)                   // 8
#define B_ROW_BYTES 2064                     // (1024+8) bf16
#define A_ROW_BYTES 272                      // (128+8) bf16
#define GRP_PLANE (16 * A_ROW_BYTES)         // 4352
#define GRP_BUFS (4 * GRP_PLANE)             // 17408
#define OFF_BHI 0
#define OFF_BLO (32 * B_ROW_BYTES)           // 66048
#define OFF_A   (2 * 32 * B_ROW_BYTES)       // 132096
#define OFF_Z   (OFF_A + 4 * GRP_BUFS)       // 201728
#define Z_STRIDE 18
#define SCAN_SMEM (OFF_Z + 64 * Z_STRIDE * 4)  // 206336

__global__ void __launch_bounds__(512) scan_kernel(const float* __restrict__ Whh) {
    extern __shared__ char smem[];
    const uint32_t sbase = smem_u32(smem);
    float* zbuf = (float*)(smem + OFF_Z);
    const int tid  = threadIdx.x;
    const int warp = tid >> 5;
    const int lane = tid & 31;
    const int gid  = warp >> 2;
    const int gtid = tid & 127;
    const int barid = 1 + gid;
    const int r_base = blockIdx.x * 16;

    for (int i = tid; i < 32 * R_SZ; i += 512) {
        int j = i >> 10;
        int k = i & 1023;
        float w = (j < 16) ? Whh[(size_t)(r_base + j) * R_SZ + k]
                           : g_Mz[(size_t)(r_base + j - 16) * R_SZ + k];
        __nv_bfloat16 h = __float2bfloat16_rn(w);
        __nv_bfloat16 l = __float2bfloat16_rn(w - __bfloat162float(h));
        *(unsigned short*)(smem + OFF_BHI + j * B_ROW_BYTES + k * 2) = __bfloat16_as_ushort(h);
        *(unsigned short*)(smem + OFF_BLO + j * B_ROW_BYTES + k * 2) = __bfloat16_as_ushort(l);
    }
    __syncthreads();

    const int m0 = gid * 16;
    const int q  = warp & 3;
    const bool is_h = (q < 2);

    const int rrow = lane >> 2;
    const int jc   = (lane & 3) * 2;
    const int rc   = (q & 1) * 8 + jc;
    const int jg   = r_base + rc;
    const int brow0 = m0 + rrow, brow1 = brow0 + 8;

    // B ldmatrix.x4 lane address: row n = q*8 + (lane&7); tile = lane>>3 selects
    // 16B k-chunk: tiles {0,1} -> k16a {b0,b1}, tiles {2,3} -> k16b {b0,b1}.
    const uint32_t b_lm = (uint32_t)(q * 8 + (lane & 7)) * B_ROW_BYTES
                        + (uint32_t)(lane >> 3) * 16;
    const uint32_t a_row_off = (uint32_t)(lane & 15) * A_ROW_BYTES + (uint32_t)(lane >> 4) * 16;
    const uint32_t grpA = (uint32_t)OFF_A + (uint32_t)gid * GRP_BUFS;

    volatile unsigned* flags   = (volatile unsigned*)g_flags;
    volatile unsigned* release = (volatile unsigned*)&g_release;

    float hold[2][2] = {};

    for (int t = 0; t < T_SZ; t++) {
        float xv[2][2];
        {
            const float* src = (is_h ? g_xh : g_xz) + (size_t)t * (B_SZ * R_SZ);
            float2 a0 = __ldg((const float2*)(src + (size_t)brow0 * R_SZ + jg));
            float2 a1 = __ldg((const float2*)(src + (size_t)brow1 * R_SZ + jg));
            xv[0][0] = a0.x; xv[0][1] = a0.y; xv[1][0] = a1.x; xv[1][1] = a1.y;
        }

        const unsigned short* hhi = g_h_hi[t & 1];
        const unsigned short* hlo = g_h_lo[t & 1];

        float d[4] = {0.0f, 0.0f, 0.0f, 0.0f};

        auto stage = [&](int buf, int kc) {
            #pragma unroll
            for (int r = 0; r < 4; r++) {
                int cid   = gtid + r * 128;
                int plane = cid >> 8;
                int rem   = cid & 255;
                int row   = rem >> 4;
                int c16   = rem & 15;
                uint32_t dA = sbase + grpA + (uint32_t)buf * (2 * GRP_PLANE)
                            + (uint32_t)plane * GRP_PLANE
                            + (uint32_t)row * A_ROW_BYTES + (uint32_t)c16 * 16;
                const unsigned short* sp = plane ? hlo : hhi;
                cp_async16(dA, sp + (size_t)(m0 + row) * R_SZ + kc + c16 * 8);
            }
        };

        stage(0, 0);
        CP_COMMIT();
        for (int c = 0; c < NCHUNK; c++) {
            if (c + 1 < NCHUNK) { stage((c + 1) & 1, (c + 1) * KC); CP_COMMIT(); CP_WAIT1(); }
            else                { CP_WAIT0(); }
            BAR_SYNC(barid, 128);

            const int buf = c & 1;
            const uint32_t a_hi_base = sbase + grpA + (uint32_t)buf * (2 * GRP_PLANE);
            const uint32_t a_lo_base = a_hi_base + GRP_PLANE;
            const uint32_t kB_chunk = (uint32_t)(c * KC) * 2;

            #pragma unroll
            for (int kb2 = 0; kb2 < KC / 32; kb2++) {
                const uint32_t kloc = (uint32_t)kb2 * 64;     // bytes (32 elems)
                uint32_t ahA[4], ahB[4], alA[4], alB[4];
                ldsm_x4(ahA, a_hi_base + a_row_off + kloc);
                ldsm_x4(ahB, a_hi_base + a_row_off + kloc + 32);
                ldsm_x4(alA, a_lo_base + a_row_off + kloc);
                ldsm_x4(alB, a_lo_base + a_row_off + kloc + 32);

                uint32_t bh[4], bl[4];
                ldsm_x4(bh, sbase + OFF_BHI + b_lm + kB_chunk + kloc);
                ldsm_x4(bl, sbase + OFF_BLO + b_lm + kB_chunk + kloc);

                // k16a
                mma_bf16(d, ahA, bh[0], bh[1]);
                mma_bf16(d, ahA, bl[0], bl[1]);
                mma_bf16(d, alA, bh[0], bh[1]);
                // k16b
                mma_bf16(d, ahB, bh[2], bh[3]);
                mma_bf16(d, ahB, bl[2], bl[3]);
                mma_bf16(d, alB, bh[2], bh[3]);
            }
            BAR_SYNC(barid, 128);
        }

        if (!is_h) {
            #pragma unroll
            for (int qq = 0; qq < 2; qq++) {
                int br = (qq == 0) ? brow0 : brow1;
                float2 zv;
                zv.x = 1.0f / (1.0f + expf(-(d[qq * 2 + 0] + xv[qq][0])));
                zv.y = 1.0f / (1.0f + expf(-(d[qq * 2 + 1] + xv[qq][1])));
                *(float2*)&zbuf[br * Z_STRIDE + rc] = zv;
            }
        }
        BAR_SYNC(barid, 128);
        if (is_h) {
            unsigned short* dhi = g_h_hi[(t + 1) & 1];
            unsigned short* dlo = g_h_lo[(t + 1) & 1];
            #pragma unroll
            for (int qq = 0; qq < 2; qq++) {
                int br = (qq == 0) ? brow0 : brow1;
                float2 zv = *(const float2*)&zbuf[br * Z_STRIDE + rc];
                float hb0 = fmaxf(d[qq * 2 + 0] + xv[qq][0], 0.0f);
                float hb1 = fmaxf(d[qq * 2 + 1] + xv[qq][1], 0.0f);
                float hn0 = zv.x * hold[qq][0] + (1.0f - zv.x) * hb0;
                float hn1 = zv.y * hold[qq][1] + (1.0f - zv.y) * hb1;
                hold[qq][0] = hn0; hold[qq][1] = hn1;
                size_t o = (size_t)br * R_SZ + jg;
                *(uint32_t*)(dhi + o) = pack2_hi(hn0, hn1);
                *(uint32_t*)(dlo + o) = pack2_lo(hn0, hn1);
                if (t == T_SZ - 1) {
                    g_hf[o] = hn0; g_hf[o + 1] = hn1;
                }
            }
        }

        // distributed-flag grid barrier over 64 CTAs
        __threadfence();
        __syncthreads();
        if (blockIdx.x == 0) {
            if (tid > 0 && tid < NCTA) {
                while (flags[tid] <= (unsigned)t) { }
            }
            __syncthreads();
            if (tid == 0) {
                __threadfence();
                *release = (unsigned)(t + 1);
            }
        } else {
            if (tid == 0) {
                flags[blockIdx.x] = (unsigned)(t + 1);
                while (*release <= (unsigned)t) { }
            }
        }
        __syncthreads();
    }
}

// ==================== Output: y = h_final @ Wy^T + by ====================
__global__ void __launch_bounds__(128) output_kernel(const float* __restrict__ Wy,
                                                     const float* __restrict__ by,
                                                     float* __restrict__ out) {
    __shared__ float shh[R_SZ];
    const int b = blockIdx.x;
    const int o = blockIdx.y * 128 + threadIdx.x;
    const float* hrow = g_hf + (size_t)b * R_SZ;
    #pragma unroll
    for (int v = 0; v < 2; v++) {
        int i4 = threadIdx.x + v * 128;
        ((float4*)shh)[i4] = *(const float4*)(hrow + i4 * 4);
    }
    __syncthreads();
    float acc = __ldg(&by[o]);
    const float* wrow = Wy + (size_t)o * R_SZ;
    #pragma unroll 8
    for (int k4 = 0; k4 < R_SZ / 4; k4++) {
        float4 h4 = ((const float4*)shh)[k4];
        float4 w4 = __ldg((const float4*)(wrow + k4 * 4));
        acc = fmaf(h4.x, w4.x, acc); acc = fmaf(h4.y, w4.y, acc);
        acc = fmaf(h4.z, w4.z, acc); acc = fmaf(h4.w, w4.w, acc);
    }
    out[(size_t)b * O_SZ + o] = acc;
}

// ==================== launch ====================
extern "C" void kernel_launch(void* const* d_in, const int* in_sizes, int n_in,
                              void* d_out, int out_size) {
    const float* x   = (const float*)d_in[0];
    const float* Wxh = (const float*)d_in[1];
    const float* bh  = (const float*)d_in[2];
    const float* Whh = (const float*)d_in[3];
    const float* Wxz = (const float*)d_in[4];
    const float* bz  = (const float*)d_in[5];
    const float* Whz = (const float*)d_in[6];
    const float* Wy  = (const float*)d_in[7];
    const float* by  = (const float*)d_in[8];
    float* out = (float*)d_out;

    static bool attr_set = false;
    if (!attr_set) {
        cudaFuncSetAttribute(scan_kernel,
                             cudaFuncAttributeMaxDynamicSharedMemorySize, SCAN_SMEM);
        cudaFuncSetAttribute(precompute_mma,
                             cudaFuncAttributeMaxDynamicSharedMemorySize, PP_SMEM);
        attr_set = true;
    }

    unsigned short *xhi_p, *xlo_p, *whi_p, *wlo_p;
    cudaGetSymbolAddress((void**)&xhi_p, g_x_hi);
    cudaGetSymbolAddress((void**)&xlo_p, g_x_lo);
    cudaGetSymbolAddress((void**)&whi_p, g_w_hi);
    cudaGetSymbolAddress((void**)&wlo_p, g_w_lo);
    split_kernel<<<(int)((size_t)M_SZ * D_SZ / 1024), 256>>>(x, xhi_p, xlo_p);
    split_kernel<<<(R_SZ * D_SZ) / 1024, 256>>>(Wxh, whi_p, wlo_p);
    split_kernel<<<(R_SZ * D_SZ) / 1024, 256>>>(Wxz, whi_p + (size_t)R_SZ * D_SZ,
                                                wlo_p + (size_t)R_SZ * D_SZ);

    // 4th launch (ncu capture slot): precompute. mz only needed before scan.
    precompute_mma<<<dim3(2048 / 128, M_SZ / 128), 512, PP_SMEM>>>(bh, bz);
    mz_kernel<<<dim3(R_SZ / 64, R_SZ / 64), 256>>>(Wxz, Whz);
    init_kernel<<<(B_SZ * R_SZ + 255) / 256, 256>>>();
    scan_kernel<<<NCTA, 512, SCAN_SMEM>>>(Whh);
    output_kernel<<<dim3(B_SZ, O_SZ / 128), 128>>>(Wy, by, out);
}

// round 11
// speedup vs baseline: 1.4030x; 1.4030x over previous
#include <cuda_runtime.h>
#include <cuda_bf16.h>
#include <cstdint>

// Problem dims
#define B_SZ 64
#define T_SZ 512
#define D_SZ 1024
#define R_SZ 1024
#define O_SZ 1024
#define M_SZ (B_SZ * T_SZ)   // 32768

// ---------------- device scratch (static: no runtime allocation) ----------------
__device__ float          g_xh[(size_t)T_SZ * B_SZ * R_SZ];   // [T][B][R]
__device__ float          g_xz[(size_t)T_SZ * B_SZ * R_SZ];   // [T][B][R]
__device__ float          g_Mz[(size_t)R_SZ * R_SZ];          // Wxz @ Whz
__device__ unsigned short g_x_hi[(size_t)M_SZ * D_SZ];        // X bf16 hi
__device__ unsigned short g_x_lo[(size_t)M_SZ * D_SZ];        // X bf16 lo
__device__ unsigned short g_w_hi[(size_t)2048 * D_SZ];        // [Wxh;Wxz] bf16 hi
__device__ unsigned short g_w_lo[(size_t)2048 * D_SZ];        // [Wxh;Wxz] bf16 lo
__device__ unsigned short g_h_hi[2][B_SZ * R_SZ];             // h bf16 hi (dbl buf)
__device__ unsigned short g_h_lo[2][B_SZ * R_SZ];             // h bf16 lo
__device__ float          g_hf[B_SZ * R_SZ];                  // final h fp32
__device__ unsigned       g_flags[128 * 32];                  // padded per-CTA step flags

// ==================== helpers ====================
__device__ __forceinline__ uint32_t smem_u32(const void* p) {
    uint32_t a;
    asm("{ .reg .u64 t; cvta.to.shared.u64 t, %1; cvt.u32.u64 %0, t; }" : "=r"(a) : "l"(p));
    return a;
}
__device__ __forceinline__ void ldsm_x4(uint32_t r[4], uint32_t addr) {
    asm volatile("ldmatrix.sync.aligned.m8n8.x4.shared.b16 {%0,%1,%2,%3}, [%4];"
                 : "=r"(r[0]), "=r"(r[1]), "=r"(r[2]), "=r"(r[3]) : "r"(addr));
}
__device__ __forceinline__ void mma_bf16(float d[4], const uint32_t a[4],
                                         uint32_t b0, uint32_t b1) {
    asm volatile("mma.sync.aligned.m16n8k16.row.col.f32.bf16.bf16.f32 "
                 "{%0,%1,%2,%3}, {%4,%5,%6,%7}, {%8,%9}, {%0,%1,%2,%3};"
                 : "+f"(d[0]), "+f"(d[1]), "+f"(d[2]), "+f"(d[3])
                 : "r"(a[0]), "r"(a[1]), "r"(a[2]), "r"(a[3]), "r"(b0), "r"(b1));
}
__device__ __forceinline__ void cp_async16(uint32_t dst, const void* src) {
    asm volatile("cp.async.cg.shared.global [%0], [%1], 16;" :: "r"(dst), "l"(src));
}
#define CP_COMMIT() asm volatile("cp.async.commit_group;" ::: "memory")
#define CP_WAIT0()  asm volatile("cp.async.wait_group 0;" ::: "memory")
#define CP_WAIT1()  asm volatile("cp.async.wait_group 1;" ::: "memory")
#define BAR_SYNC(id, cnt) asm volatile("bar.sync %0, %1;" :: "r"(id), "r"(cnt) : "memory")

__device__ __forceinline__ uint32_t pack2_hi(float a, float b) {
    return (uint32_t)__bfloat16_as_ushort(__float2bfloat16_rn(a))
         | ((uint32_t)__bfloat16_as_ushort(__float2bfloat16_rn(b)) << 16);
}
__device__ __forceinline__ uint32_t pack2_lo(float a, float b) {
    float ra = a - __bfloat162float(__float2bfloat16_rn(a));
    float rb = b - __bfloat162float(__float2bfloat16_rn(b));
    return pack2_hi(ra, rb);
}

// ==================== init ====================
__global__ void init_kernel() {
    int i = blockIdx.x * blockDim.x + threadIdx.x;
    if (i < B_SZ * R_SZ) { g_h_hi[0][i] = 0; g_h_lo[0][i] = 0; }
    if (i < 128 * 32) g_flags[i] = 0u;
}

// ==================== fp32 -> bf16 hi/lo split ====================
__global__ void __launch_bounds__(256) split_kernel(const float* __restrict__ src,
                                                    unsigned short* __restrict__ hi,
                                                    unsigned short* __restrict__ lo) {
    size_t i = ((size_t)blockIdx.x * 256 + threadIdx.x) * 4;
    float4 v = *(const float4*)(src + i);
    uint2 h, l;
    h.x = pack2_hi(v.x, v.y); h.y = pack2_hi(v.z, v.w);
    l.x = pack2_lo(v.x, v.y); l.y = pack2_lo(v.z, v.w);
    *(uint2*)(hi + i) = h;
    *(uint2*)(lo + i) = l;
}

// ==================== Mz = Wxz @ Whz (SIMT fp32) ====================
__global__ void __launch_bounds__(256) mz_kernel(const float* __restrict__ Wxz,
                                                 const float* __restrict__ Whz) {
    __shared__ float As[16][68];
    __shared__ float Bs[16][68];
    const int tid = threadIdx.x;
    const int i0 = blockIdx.x * 64;
    const int j0 = blockIdx.y * 64;
    const int tx = tid & 15;
    const int ty = tid >> 4;
    float acc[4][4] = {};

    for (int k0 = 0; k0 < R_SZ; k0 += 16) {
        {
            int row = tid >> 2;
            int c4  = (tid & 3) * 4;
            float4 a = *(const float4*)(Wxz + (size_t)(i0 + row) * R_SZ + k0 + c4);
            As[c4 + 0][row] = a.x; As[c4 + 1][row] = a.y;
            As[c4 + 2][row] = a.z; As[c4 + 3][row] = a.w;
        }
        {
            int kk = tid >> 4;
            int j4 = (tid & 15) * 4;
            float4 b = *(const float4*)(Whz + (size_t)(k0 + kk) * R_SZ + j0 + j4);
            *(float4*)&Bs[kk][j4] = b;
        }
        __syncthreads();
        #pragma unroll
        for (int kk = 0; kk < 16; kk++) {
            float ar[4], br[4];
            *(float4*)ar = *(const float4*)&As[kk][ty * 4];
            *(float4*)br = *(const float4*)&Bs[kk][tx * 4];
            #pragma unroll
            for (int i = 0; i < 4; i++)
                #pragma unroll
                for (int j = 0; j < 4; j++)
                    acc[i][j] = fmaf(ar[i], br[j], acc[i][j]);
        }
        __syncthreads();
    }
    #pragma unroll
    for (int i = 0; i < 4; i++) {
        float4 v = make_float4(acc[i][0], acc[i][1], acc[i][2], acc[i][3]);
        *(float4*)(g_Mz + (size_t)(i0 + ty * 4 + i) * R_SZ + j0 + tx * 4) = v;
    }
}

// ==================== Precompute xh/xz with HMMA + cp.async ====================
// 128x128 tile, BK=32, 512 threads (16 warps = 4m x 4n), warp tile 32x32.
#define PP_ROW_B 80
#define PP_PLANE 10240
#define PP_SMEM (8 * PP_PLANE)

__global__ void __launch_bounds__(512, 1) precompute_mma(const float* __restrict__ bh,
                                                         const float* __restrict__ bz) {
    extern __shared__ char psm[];
    const uint32_t sb = smem_u32(psm);
    const int tid = threadIdx.x, warp = tid >> 5, lane = tid & 31;
    const long m_blk = (long)blockIdx.y * 128;
    const int  n_blk = blockIdx.x * 128;

    const float* bias; float* dst; int rb;
    if (n_blk < R_SZ) { bias = bh; dst = g_xh; rb = n_blk; }
    else              { bias = bz; dst = g_xz; rb = n_blk - R_SZ; }

    const int m0w = (warp & 3) * 32;
    const int n0w = (warp >> 2) * 32;

    float acc[2][4][4];
    #pragma unroll
    for (int a = 0; a < 2; a++)
        #pragma unroll
        for (int b = 0; b < 4; b++)
            #pragma unroll
            for (int c = 0; c < 4; c++) acc[a][b][c] = 0.0f;

    auto stage = [&](int buf, int k0) {
        int row = tid >> 2;
        int qt  = tid & 3;
        size_t sa = (size_t)(m_blk + row) * D_SZ + k0 + qt * 8;
        size_t sw = (size_t)(n_blk + row) * D_SZ + k0 + qt * 8;
        uint32_t o = (uint32_t)row * PP_ROW_B + (uint32_t)qt * 16;
        uint32_t base = sb + (uint32_t)(buf * 4) * PP_PLANE;
        cp_async16(base + o,                 g_x_hi + sa);
        cp_async16(base + PP_PLANE + o,      g_x_lo + sa);
        cp_async16(base + 2 * PP_PLANE + o,  g_w_hi + sw);
        cp_async16(base + 3 * PP_PLANE + o,  g_w_lo + sw);
    };

    int buf = 0;
    stage(0, 0);
    CP_COMMIT();
    for (int s = 0; s < D_SZ / 32; s++) {
        if (s + 1 < D_SZ / 32) { stage(buf ^ 1, (s + 1) * 32); CP_COMMIT(); CP_WAIT1(); }
        else                   { CP_WAIT0(); }
        __syncthreads();

        const uint32_t AhS = sb + (uint32_t)((buf * 4 + 0) * PP_PLANE);
        const uint32_t AlS = AhS + PP_PLANE;
        const char* Bh = psm + (buf * 4 + 2) * PP_PLANE;
        const char* Bl = Bh + PP_PLANE;
        #pragma unroll
        for (int k16 = 0; k16 < 2; k16++) {
            uint32_t ahi[2][4], alo[2][4];
            #pragma unroll
            for (int mi = 0; mi < 2; mi++) {
                uint32_t ar = (uint32_t)(m0w + mi * 16 + (lane & 15)) * PP_ROW_B
                            + (uint32_t)(lane >> 4) * 16 + (uint32_t)k16 * 32;
                ldsm_x4(ahi[mi], AhS + ar);
                ldsm_x4(alo[mi], AlS + ar);
            }
            uint32_t bhw[4][2], blw[4][2];
            #pragma unroll
            for (int ni = 0; ni < 4; ni++) {
                uint32_t bo = (uint32_t)(n0w + ni * 8 + (lane >> 2)) * PP_ROW_B
                            + (uint32_t)((lane & 3) * 2) * 2 + (uint32_t)k16 * 32;
                bhw[ni][0] = *(const uint32_t*)(Bh + bo);
                bhw[ni][1] = *(const uint32_t*)(Bh + bo + 16);
                blw[ni][0] = *(const uint32_t*)(Bl + bo);
                blw[ni][1] = *(const uint32_t*)(Bl + bo + 16);
            }
            #pragma unroll
            for (int mi = 0; mi < 2; mi++)
                #pragma unroll
                for (int ni = 0; ni < 4; ni++) {
                    mma_bf16(acc[mi][ni], ahi[mi], bhw[ni][0], bhw[ni][1]);
                    mma_bf16(acc[mi][ni], ahi[mi], blw[ni][0], blw[ni][1]);
                    mma_bf16(acc[mi][ni], alo[mi], bhw[ni][0], bhw[ni][1]);
                }
        }
        __syncthreads();
        buf ^= 1;
    }

    #pragma unroll
    for (int ni = 0; ni < 4; ni++) {
        int col = n0w + ni * 8 + (lane & 3) * 2;
        float2 bv = *(const float2*)(bias + rb + col);
        #pragma unroll
        for (int mi = 0; mi < 2; mi++) {
            #pragma unroll
            for (int half = 0; half < 2; half++) {
                long m = m_blk + m0w + mi * 16 + (lane >> 2) + half * 8;
                int b = (int)(m >> 9), t = (int)(m & 511);
                float2 v;
                v.x = acc[mi][ni][half * 2 + 0] + bv.x;
                v.y = acc[mi][ni][half * 2 + 1] + bv.y;
                *(float2*)(dst + ((long)t * B_SZ + b) * R_SZ + rb + col) = v;
            }
        }
    }
}

// ==================== Persistent warp-MMA scan: 128 CTAs (batch-half x r-slice16) ====================
// CTA c: batch rows [32*(c&1), +32), r-slice [(c>>1)*16, +16). 256 threads = 2 groups x 4 warps.
// Group g owns m-stripe rows [m_base+16g, +16); warp q in group: B rows q*8..q*8+8
// (q<2 -> h n-tiles, q>=2 -> z n-tiles). B weights SMEM bf16 hi/lo; B frags via ldmatrix.
#define NCTA 128
#define KC 128
#define NCHUNK (R_SZ / KC)                   // 8
#define B_ROW_BYTES 2064                     // (1024+8) bf16
#define A_ROW_BYTES 272                      // (128+8) bf16
#define GRP_PLANE (16 * A_ROW_BYTES)         // 4352
#define GRP_BUFS (4 * GRP_PLANE)             // 17408
#define OFF_BHI 0
#define OFF_BLO (32 * B_ROW_BYTES)           // 66048
#define OFF_A   (2 * 32 * B_ROW_BYTES)       // 132096
#define OFF_Z   (OFF_A + 2 * GRP_BUFS)       // 166912
#define Z_STRIDE 18
#define SCAN_SMEM (OFF_Z + 32 * Z_STRIDE * 4)  // 169216

__global__ void __launch_bounds__(256) scan_kernel(const float* __restrict__ Whh) {
    extern __shared__ char smem[];
    const uint32_t sbase = smem_u32(smem);
    float* zbuf = (float*)(smem + OFF_Z);
    const int tid  = threadIdx.x;
    const int warp = tid >> 5;
    const int lane = tid & 31;
    const int gid  = warp >> 2;              // group 0..1 (m-stripe)
    const int gtid = tid & 127;
    const int barid = 1 + gid;
    const int bh_half = blockIdx.x & 1;      // batch half
    const int m_base  = bh_half * 32;
    const int r_base  = (blockIdx.x >> 1) * 16;

    // one-time: weights -> SMEM bf16 hi/lo (32 rows: [Whh 16; Mz 16])
    for (int i = tid; i < 32 * R_SZ; i += 256) {
        int j = i >> 10;
        int k = i & 1023;
        float w = (j < 16) ? Whh[(size_t)(r_base + j) * R_SZ + k]
                           : g_Mz[(size_t)(r_base + j - 16) * R_SZ + k];
        __nv_bfloat16 h = __float2bfloat16_rn(w);
        __nv_bfloat16 l = __float2bfloat16_rn(w - __bfloat162float(h));
        *(unsigned short*)(smem + OFF_BHI + j * B_ROW_BYTES + k * 2) = __bfloat16_as_ushort(h);
        *(unsigned short*)(smem + OFF_BLO + j * B_ROW_BYTES + k * 2) = __bfloat16_as_ushort(l);
    }
    __syncthreads();

    const int q  = warp & 3;                 // 0,1 = h tiles; 2,3 = z tiles
    const bool is_h = (q < 2);

    const int rrow = lane >> 2;              // 0..7
    const int jc   = (lane & 3) * 2;         // 0,2,4,6
    const int rc   = (q & 1) * 8 + jc;       // col within 16-slice
    const int jg   = r_base + rc;            // global r
    const int lrow0 = gid * 16 + rrow;       // CTA-local batch row
    const int lrow1 = lrow0 + 8;
    const int brow0 = m_base + lrow0, brow1 = m_base + lrow1;

    // B ldmatrix.x4: row = q*8 + (lane&7); lane>>3 selects 16B k-chunk (2 k16 slices)
    const uint32_t b_lm = (uint32_t)(q * 8 + (lane & 7)) * B_ROW_BYTES
                        + (uint32_t)(lane >> 3) * 16;
    const uint32_t a_row_off = (uint32_t)(lane & 15) * A_ROW_BYTES + (uint32_t)(lane >> 4) * 16;
    const uint32_t grpA = (uint32_t)OFF_A + (uint32_t)gid * GRP_BUFS;

    volatile unsigned* flags = (volatile unsigned*)g_flags;

    float hold[2][2] = {};

    for (int t = 0; t < T_SZ; t++) {
        float xv[2][2];
        {
            const float* src = (is_h ? g_xh : g_xz) + (size_t)t * (B_SZ * R_SZ);
            float2 a0 = __ldg((const float2*)(src + (size_t)brow0 * R_SZ + jg));
            float2 a1 = __ldg((const float2*)(src + (size_t)brow1 * R_SZ + jg));
            xv[0][0] = a0.x; xv[0][1] = a0.y; xv[1][0] = a1.x; xv[1][1] = a1.y;
        }

        const unsigned short* hhi = g_h_hi[t & 1];
        const unsigned short* hlo = g_h_lo[t & 1];

        float d0[4] = {0.f, 0.f, 0.f, 0.f};
        float d1[4] = {0.f, 0.f, 0.f, 0.f};

        // group stages its 16 rows x KC x 2 planes = 512 x 16B over 128 threads
        auto stage = [&](int buf, int kc) {
            #pragma unroll
            for (int r = 0; r < 4; r++) {
                int cid   = gtid + r * 128;
                int plane = cid >> 8;
                int rem   = cid & 255;
                int row   = rem >> 4;
                int c16   = rem & 15;
                uint32_t dA = sbase + grpA + (uint32_t)buf * (2 * GRP_PLANE)
                            + (uint32_t)plane * GRP_PLANE
                            + (uint32_t)row * A_ROW_BYTES + (uint32_t)c16 * 16;
                const unsigned short* sp = plane ? hlo : hhi;
                cp_async16(dA, sp + (size_t)(m_base + gid * 16 + row) * R_SZ + kc + c16 * 8);
            }
        };

        stage(0, 0);
        CP_COMMIT();
        for (int c = 0; c < NCHUNK; c++) {
            if (c + 1 < NCHUNK) { stage((c + 1) & 1, (c + 1) * KC); CP_COMMIT(); CP_WAIT1(); }
            else                { CP_WAIT0(); }
            BAR_SYNC(barid, 128);

            const int buf = c & 1;
            const uint32_t a_hi_base = sbase + grpA + (uint32_t)buf * (2 * GRP_PLANE);
            const uint32_t a_lo_base = a_hi_base + GRP_PLANE;
            const uint32_t kB_chunk = (uint32_t)(c * KC) * 2;

            #pragma unroll
            for (int kb2 = 0; kb2 < KC / 32; kb2++) {
                const uint32_t kloc = (uint32_t)kb2 * 64;
                uint32_t ahA[4], ahB[4], alA[4], alB[4];
                ldsm_x4(ahA, a_hi_base + a_row_off + kloc);
                ldsm_x4(ahB, a_hi_base + a_row_off + kloc + 32);
                ldsm_x4(alA, a_lo_base + a_row_off + kloc);
                ldsm_x4(alB, a_lo_base + a_row_off + kloc + 32);

                uint32_t bh[4], bl[4];
                ldsm_x4(bh, sbase + OFF_BHI + b_lm + kB_chunk + kloc);
                ldsm_x4(bl, sbase + OFF_BLO + b_lm + kB_chunk + kloc);

                // two independent accumulator chains (d0: k16a, d1: k16b)
                mma_bf16(d0, ahA, bh[0], bh[1]);
                mma_bf16(d1, ahB, bh[2], bh[3]);
                mma_bf16(d0, ahA, bl[0], bl[1]);
                mma_bf16(d1, ahB, bl[2], bl[3]);
                mma_bf16(d0, alA, bh[0], bh[1]);
                mma_bf16(d1, alB, bh[2], bh[3]);
            }
            BAR_SYNC(barid, 128);
        }

        float d[4];
        #pragma unroll
        for (int i = 0; i < 4; i++) d[i] = d0[i] + d1[i];

        if (!is_h) {
            #pragma unroll
            for (int qq = 0; qq < 2; qq++) {
                int lr = (qq == 0) ? lrow0 : lrow1;
                float2 zv;
                zv.x = 1.0f / (1.0f + expf(-(d[qq * 2 + 0] + xv[qq][0])));
                zv.y = 1.0f / (1.0f + expf(-(d[qq * 2 + 1] + xv[qq][1])));
                *(float2*)&zbuf[lr * Z_STRIDE + rc] = zv;
            }
        }
        BAR_SYNC(barid, 128);
        if (is_h) {
            unsigned short* dhi = g_h_hi[(t + 1) & 1];
            unsigned short* dlo = g_h_lo[(t + 1) & 1];
            #pragma unroll
            for (int qq = 0; qq < 2; qq++) {
                int lr = (qq == 0) ? lrow0 : lrow1;
                int br = m_base + lr;
                float2 zv = *(const float2*)&zbuf[lr * Z_STRIDE + rc];
                float hb0 = fmaxf(d[qq * 2 + 0] + xv[qq][0], 0.0f);
                float hb1 = fmaxf(d[qq * 2 + 1] + xv[qq][1], 0.0f);
                float hn0 = zv.x * hold[qq][0] + (1.0f - zv.x) * hb0;
                float hn1 = zv.y * hold[qq][1] + (1.0f - zv.y) * hb1;
                hold[qq][0] = hn0; hold[qq][1] = hn1;
                size_t o = (size_t)br * R_SZ + jg;
                *(uint32_t*)(dhi + o) = pack2_hi(hn0, hn1);
                *(uint32_t*)(dlo + o) = pack2_lo(hn0, hn1);
                if (t == T_SZ - 1) {
                    g_hf[o] = hn0; g_hf[o + 1] = hn1;
                }
            }
        }

        // all-poll-all grid barrier: publish flag, every CTA polls all 128 in parallel
        __threadfence();
        __syncthreads();
        if (tid == 0) flags[blockIdx.x * 32] = (unsigned)(t + 1);
        if (tid < NCTA) {
            while (flags[tid * 32] <= (unsigned)t) { }
        }
        __syncthreads();
    }
}

// ==================== Output: y = h_final @ Wy^T + by ====================
__global__ void __launch_bounds__(128) output_kernel(const float* __restrict__ Wy,
                                                     const float* __restrict__ by,
                                                     float* __restrict__ out) {
    __shared__ float shh[R_SZ];
    const int b = blockIdx.x;
    const int o = blockIdx.y * 128 + threadIdx.x;
    const float* hrow = g_hf + (size_t)b * R_SZ;
    #pragma unroll
    for (int v = 0; v < 2; v++) {
        int i4 = threadIdx.x + v * 128;
        ((float4*)shh)[i4] = *(const float4*)(hrow + i4 * 4);
    }
    __syncthreads();
    float acc = __ldg(&by[o]);
    const float* wrow = Wy + (size_t)o * R_SZ;
    #pragma unroll 8
    for (int k4 = 0; k4 < R_SZ / 4; k4++) {
        float4 h4 = ((const float4*)shh)[k4];
        float4 w4 = __ldg((const float4*)(wrow + k4 * 4));
        acc = fmaf(h4.x, w4.x, acc); acc = fmaf(h4.y, w4.y, acc);
        acc = fmaf(h4.z, w4.z, acc); acc = fmaf(h4.w, w4.w, acc);
    }
    out[(size_t)b * O_SZ + o] = acc;
}

// ==================== launch ====================
extern "C" void kernel_launch(void* const* d_in, const int* in_sizes, int n_in,
                              void* d_out, int out_size) {
    const float* x   = (const float*)d_in[0];
    const float* Wxh = (const float*)d_in[1];
    const float* bh  = (const float*)d_in[2];
    const float* Whh = (const float*)d_in[3];
    const float* Wxz = (const float*)d_in[4];
    const float* bz  = (const float*)d_in[5];
    const float* Whz = (const float*)d_in[6];
    const float* Wy  = (const float*)d_in[7];
    const float* by  = (const float*)d_in[8];
    float* out = (float*)d_out;

    static bool attr_set = false;
    if (!attr_set) {
        cudaFuncSetAttribute(scan_kernel,
                             cudaFuncAttributeMaxDynamicSharedMemorySize, SCAN_SMEM);
        cudaFuncSetAttribute(precompute_mma,
                             cudaFuncAttributeMaxDynamicSharedMemorySize, PP_SMEM);
        attr_set = true;
    }

    unsigned short *xhi_p, *xlo_p, *whi_p, *wlo_p;
    cudaGetSymbolAddress((void**)&xhi_p, g_x_hi);
    cudaGetSymbolAddress((void**)&xlo_p, g_x_lo);
    cudaGetSymbolAddress((void**)&whi_p, g_w_hi);
    cudaGetSymbolAddress((void**)&wlo_p, g_w_lo);
    split_kernel<<<(int)((size_t)M_SZ * D_SZ / 1024), 256>>>(x, xhi_p, xlo_p);
    split_kernel<<<(R_SZ * D_SZ) / 1024, 256>>>(Wxh, whi_p, wlo_p);
    split_kernel<<<(R_SZ * D_SZ) / 1024, 256>>>(Wxz, whi_p + (size_t)R_SZ * D_SZ,
                                                wlo_p + (size_t)R_SZ * D_SZ);

    precompute_mma<<<dim3(2048 / 128, M_SZ / 128), 512, PP_SMEM>>>(bh, bz);
    mz_kernel<<<dim3(R_SZ / 64, R_SZ / 64), 256>>>(Wxz, Whz);
    init_kernel<<<(B_SZ * R_SZ + 255) / 256, 256>>>();
    scan_kernel<<<NCTA, 256, SCAN_SMEM>>>(Whh);
    output_kernel<<<dim3(B_SZ, O_SZ / 128), 128>>>(Wy, by, out);
}

// round 12
// speedup vs baseline: 1.5399x; 1.0976x over previous
#include <cuda_runtime.h>
#include <cuda_bf16.h>
#include <cstdint>

// Problem dims
#define B_SZ 64
#define T_SZ 512
#define D_SZ 1024
#define R_SZ 1024
#define O_SZ 1024
#define M_SZ (B_SZ * T_SZ)   // 32768

// ---------------- device scratch (static: no runtime allocation) ----------------
__device__ float          g_xh[(size_t)T_SZ * B_SZ * R_SZ];   // [T][B][R]
__device__ float          g_xz[(size_t)T_SZ * B_SZ * R_SZ];   // [T][B][R]
__device__ float          g_Mz[(size_t)R_SZ * R_SZ];          // Wxz @ Whz
__device__ unsigned short g_x_hi[(size_t)M_SZ * D_SZ];        // X bf16 hi
__device__ unsigned short g_x_lo[(size_t)M_SZ * D_SZ];        // X bf16 lo
__device__ unsigned short g_w_hi[(size_t)2048 * D_SZ];        // [Wxh;Wxz] bf16 hi
__device__ unsigned short g_w_lo[(size_t)2048 * D_SZ];        // [Wxh;Wxz] bf16 lo
__device__ unsigned short g_h_hi[2][B_SZ * R_SZ];             // h bf16 hi (dbl buf)
__device__ unsigned short g_h_lo[2][B_SZ * R_SZ];             // h bf16 lo
__device__ float          g_hf[B_SZ * R_SZ];                  // final h fp32
__device__ unsigned       g_flags[128 * 32];                  // padded per-CTA step flags

// ==================== helpers ====================
__device__ __forceinline__ uint32_t smem_u32(const void* p) {
    uint32_t a;
    asm("{ .reg .u64 t; cvta.to.shared.u64 t, %1; cvt.u32.u64 %0, t; }" : "=r"(a) : "l"(p));
    return a;
}
__device__ __forceinline__ void ldsm_x4(uint32_t r[4], uint32_t addr) {
    asm volatile("ldmatrix.sync.aligned.m8n8.x4.shared.b16 {%0,%1,%2,%3}, [%4];"
                 : "=r"(r[0]), "=r"(r[1]), "=r"(r[2]), "=r"(r[3]) : "r"(addr));
}
__device__ __forceinline__ void mma_bf16(float d[4], const uint32_t a[4],
                                         uint32_t b0, uint32_t b1) {
    asm volatile("mma.sync.aligned.m16n8k16.row.col.f32.bf16.bf16.f32 "
                 "{%0,%1,%2,%3}, {%4,%5,%6,%7}, {%8,%9}, {%0,%1,%2,%3};"
                 : "+f"(d[0]), "+f"(d[1]), "+f"(d[2]), "+f"(d[3])
                 : "r"(a[0]), "r"(a[1]), "r"(a[2]), "r"(a[3]), "r"(b0), "r"(b1));
}
__device__ __forceinline__ void cp_async16(uint32_t dst, const void* src) {
    asm volatile("cp.async.cg.shared.global [%0], [%1], 16;" :: "r"(dst), "l"(src));
}
#define CP_COMMIT() asm volatile("cp.async.commit_group;" ::: "memory")
#define CP_WAIT0()  asm volatile("cp.async.wait_group 0;" ::: "memory")
#define CP_WAIT1()  asm volatile("cp.async.wait_group 1;" ::: "memory")
#define BAR_SYNC(id, cnt) asm volatile("bar.sync %0, %1;" :: "r"(id), "r"(cnt) : "memory")

__device__ __forceinline__ uint32_t pack2_hi(float a, float b) {
    return (uint32_t)__bfloat16_as_ushort(__float2bfloat16_rn(a))
         | ((uint32_t)__bfloat16_as_ushort(__float2bfloat16_rn(b)) << 16);
}
__device__ __forceinline__ uint32_t pack2_lo(float a, float b) {
    float ra = a - __bfloat162float(__float2bfloat16_rn(a));
    float rb = b - __bfloat162float(__float2bfloat16_rn(b));
    return pack2_hi(ra, rb);
}

// ==================== init ====================
__global__ void init_kernel() {
    int i = blockIdx.x * blockDim.x + threadIdx.x;
    if (i < B_SZ * R_SZ) { g_h_hi[0][i] = 0; g_h_lo[0][i] = 0; }
    if (i < 128 * 32) g_flags[i] = 0u;
}

// ==================== fp32 -> bf16 hi/lo split ====================
__global__ void __launch_bounds__(256) split_kernel(const float* __restrict__ src,
                                                    unsigned short* __restrict__ hi,
                                                    unsigned short* __restrict__ lo) {
    size_t i = ((size_t)blockIdx.x * 256 + threadIdx.x) * 4;
    float4 v = *(const float4*)(src + i);
    uint2 h, l;
    h.x = pack2_hi(v.x, v.y); h.y = pack2_hi(v.z, v.w);
    l.x = pack2_lo(v.x, v.y); l.y = pack2_lo(v.z, v.w);
    *(uint2*)(hi + i) = h;
    *(uint2*)(lo + i) = l;
}

// ==================== Mz = Wxz @ Whz (SIMT fp32) ====================
__global__ void __launch_bounds__(256) mz_kernel(const float* __restrict__ Wxz,
                                                 const float* __restrict__ Whz) {
    __shared__ float As[16][68];
    __shared__ float Bs[16][68];
    const int tid = threadIdx.x;
    const int i0 = blockIdx.x * 64;
    const int j0 = blockIdx.y * 64;
    const int tx = tid & 15;
    const int ty = tid >> 4;
    float acc[4][4] = {};

    for (int k0 = 0; k0 < R_SZ; k0 += 16) {
        {
            int row = tid >> 2;
            int c4  = (tid & 3) * 4;
            float4 a = *(const float4*)(Wxz + (size_t)(i0 + row) * R_SZ + k0 + c4);
            As[c4 + 0][row] = a.x; As[c4 + 1][row] = a.y;
            As[c4 + 2][row] = a.z; As[c4 + 3][row] = a.w;
        }
        {
            int kk = tid >> 4;
            int j4 = (tid & 15) * 4;
            float4 b = *(const float4*)(Whz + (size_t)(k0 + kk) * R_SZ + j0 + j4);
            *(float4*)&Bs[kk][j4] = b;
        }
        __syncthreads();
        #pragma unroll
        for (int kk = 0; kk < 16; kk++) {
            float ar[4], br[4];
            *(float4*)ar = *(const float4*)&As[kk][ty * 4];
            *(float4*)br = *(const float4*)&Bs[kk][tx * 4];
            #pragma unroll
            for (int i = 0; i < 4; i++)
                #pragma unroll
                for (int j = 0; j < 4; j++)
                    acc[i][j] = fmaf(ar[i], br[j], acc[i][j]);
        }
        __syncthreads();
    }
    #pragma unroll
    for (int i = 0; i < 4; i++) {
        float4 v = make_float4(acc[i][0], acc[i][1], acc[i][2], acc[i][3]);
        *(float4*)(g_Mz + (size_t)(i0 + ty * 4 + i) * R_SZ + j0 + tx * 4) = v;
    }
}

// ==================== Precompute xh/xz with HMMA + cp.async ====================
// 128x128 tile, BK=32, 512 threads (16 warps = 4m x 4n), warp tile 32x32.
#define PP_ROW_B 80
#define PP_PLANE 10240
#define PP_SMEM (8 * PP_PLANE)

__global__ void __launch_bounds__(512, 1) precompute_mma(const float* __restrict__ bh,
                                                         const float* __restrict__ bz) {
    extern __shared__ char psm[];
    const uint32_t sb = smem_u32(psm);
    const int tid = threadIdx.x, warp = tid >> 5, lane = tid & 31;
    const long m_blk = (long)blockIdx.y * 128;
    const int  n_blk = blockIdx.x * 128;

    const float* bias; float* dst; int rb;
    if (n_blk < R_SZ) { bias = bh; dst = g_xh; rb = n_blk; }
    else              { bias = bz; dst = g_xz; rb = n_blk - R_SZ; }

    const int m0w = (warp & 3) * 32;
    const int n0w = (warp >> 2) * 32;

    float acc[2][4][4];
    #pragma unroll
    for (int a = 0; a < 2; a++)
        #pragma unroll
        for (int b = 0; b < 4; b++)
            #pragma unroll
            for (int c = 0; c < 4; c++) acc[a][b][c] = 0.0f;

    auto stage = [&](int buf, int k0) {
        int row = tid >> 2;
        int qt  = tid & 3;
        size_t sa = (size_t)(m_blk + row) * D_SZ + k0 + qt * 8;
        size_t sw = (size_t)(n_blk + row) * D_SZ + k0 + qt * 8;
        uint32_t o = (uint32_t)row * PP_ROW_B + (uint32_t)qt * 16;
        uint32_t base = sb + (uint32_t)(buf * 4) * PP_PLANE;
        cp_async16(base + o,                 g_x_hi + sa);
        cp_async16(base + PP_PLANE + o,      g_x_lo + sa);
        cp_async16(base + 2 * PP_PLANE + o,  g_w_hi + sw);
        cp_async16(base + 3 * PP_PLANE + o,  g_w_lo + sw);
    };

    int buf = 0;
    stage(0, 0);
    CP_COMMIT();
    for (int s = 0; s < D_SZ / 32; s++) {
        if (s + 1 < D_SZ / 32) { stage(buf ^ 1, (s + 1) * 32); CP_COMMIT(); CP_WAIT1(); }
        else                   { CP_WAIT0(); }
        __syncthreads();

        const uint32_t AhS = sb + (uint32_t)((buf * 4 + 0) * PP_PLANE);
        const uint32_t AlS = AhS + PP_PLANE;
        const char* Bh = psm + (buf * 4 + 2) * PP_PLANE;
        const char* Bl = Bh + PP_PLANE;
        #pragma unroll
        for (int k16 = 0; k16 < 2; k16++) {
            uint32_t ahi[2][4], alo[2][4];
            #pragma unroll
            for (int mi = 0; mi < 2; mi++) {
                uint32_t ar = (uint32_t)(m0w + mi * 16 + (lane & 15)) * PP_ROW_B
                            + (uint32_t)(lane >> 4) * 16 + (uint32_t)k16 * 32;
                ldsm_x4(ahi[mi], AhS + ar);
                ldsm_x4(alo[mi], AlS + ar);
            }
            uint32_t bhw[4][2], blw[4][2];
            #pragma unroll
            for (int ni = 0; ni < 4; ni++) {
                uint32_t bo = (uint32_t)(n0w + ni * 8 + (lane >> 2)) * PP_ROW_B
                            + (uint32_t)((lane & 3) * 2) * 2 + (uint32_t)k16 * 32;
                bhw[ni][0] = *(const uint32_t*)(Bh + bo);
                bhw[ni][1] = *(const uint32_t*)(Bh + bo + 16);
                blw[ni][0] = *(const uint32_t*)(Bl + bo);
                blw[ni][1] = *(const uint32_t*)(Bl + bo + 16);
            }
            #pragma unroll
            for (int mi = 0; mi < 2; mi++)
                #pragma unroll
                for (int ni = 0; ni < 4; ni++) {
                    mma_bf16(acc[mi][ni], ahi[mi], bhw[ni][0], bhw[ni][1]);
                    mma_bf16(acc[mi][ni], ahi[mi], blw[ni][0], blw[ni][1]);
                    mma_bf16(acc[mi][ni], alo[mi], bhw[ni][0], bhw[ni][1]);
                }
        }
        __syncthreads();
        buf ^= 1;
    }

    #pragma unroll
    for (int ni = 0; ni < 4; ni++) {
        int col = n0w + ni * 8 + (lane & 3) * 2;
        float2 bv = *(const float2*)(bias + rb + col);
        #pragma unroll
        for (int mi = 0; mi < 2; mi++) {
            #pragma unroll
            for (int half = 0; half < 2; half++) {
                long m = m_blk + m0w + mi * 16 + (lane >> 2) + half * 8;
                int b = (int)(m >> 9), t = (int)(m & 511);
                float2 v;
                v.x = acc[mi][ni][half * 2 + 0] + bv.x;
                v.y = acc[mi][ni][half * 2 + 1] + bv.y;
                *(float2*)(dst + ((long)t * B_SZ + b) * R_SZ + rb + col) = v;
            }
        }
    }
}

// ==================== Persistent scan: 128 CTAs, 512 thr, K-split tier-groups ====================
// CTA c: batch rows [32*(c&1), +32), r-slice [(c>>1)*16, +16).
// 16 warps = 2 m-stripe groups (gid) x 2 K-tiers (tier) x 4 roles (q).
// Tier-group tg = warp>>2 (128 contiguous threads): stages + computes chunks c ≡ tier (mod 2)
// in its private double-buffered A region, synced by named barrier 1+tg.
// Per-step SMEM reduction combines the two K-tiers; tier-0 h-warps apply the gate.
#define NCTA 128
#define KC 128
#define NCHUNK (R_SZ / KC)                   // 8 total, 4 per tier
#define B_ROW_BYTES 2064                     // (1024+8) bf16
#define A_ROW_BYTES 272                      // (128+8) bf16
#define TG_PLANE (16 * A_ROW_BYTES)          // 4352
#define TG_BUFS (4 * TG_PLANE)               // 17408 [buf0 hi, buf0 lo, buf1 hi, buf1 lo]
#define OFF_BHI 0
#define OFF_BLO (32 * B_ROW_BYTES)           // 66048
#define OFF_A   (2 * 32 * B_ROW_BYTES)       // 132096
#define OFF_RED (OFF_A + 4 * TG_BUFS)        // 201728
#define SCAN_SMEM (OFF_RED + 16 * 32 * 16)   // 209920

__global__ void __launch_bounds__(512) scan_kernel(const float* __restrict__ Whh) {
    extern __shared__ char smem[];
    const uint32_t sbase = smem_u32(smem);
    float4* redbuf = (float4*)(smem + OFF_RED);
    const int tid  = threadIdx.x;
    const int warp = tid >> 5;
    const int lane = tid & 31;
    const int gid  = warp >> 3;              // m-stripe group 0..1
    const int tier = (warp >> 2) & 1;        // K-tier 0..1
    const int q    = warp & 3;               // role: 0,1 h; 2,3 z
    const int tg   = warp >> 2;              // tier-group 0..3
    const int gtid = tid & 127;              // thread within tier-group
    const int barid = 1 + tg;
    const int m_base = (blockIdx.x & 1) * 32;
    const int r_base = (blockIdx.x >> 1) * 16;

    // one-time: weights -> SMEM bf16 hi/lo (32 rows: [Whh 16; Mz 16])
    for (int i = tid; i < 32 * R_SZ; i += 512) {
        int j = i >> 10;
        int k = i & 1023;
        float w = (j < 16) ? Whh[(size_t)(r_base + j) * R_SZ + k]
                           : g_Mz[(size_t)(r_base + j - 16) * R_SZ + k];
        __nv_bfloat16 h = __float2bfloat16_rn(w);
        __nv_bfloat16 l = __float2bfloat16_rn(w - __bfloat162float(h));
        *(unsigned short*)(smem + OFF_BHI + j * B_ROW_BYTES + k * 2) = __bfloat16_as_ushort(h);
        *(unsigned short*)(smem + OFF_BLO + j * B_ROW_BYTES + k * 2) = __bfloat16_as_ushort(l);
    }
    __syncthreads();

    const bool is_h = (q < 2);
    const bool gate_owner = (tier == 0) && is_h;

    const int rrow = lane >> 2;              // 0..7
    const int jc   = (lane & 3) * 2;         // 0,2,4,6
    const int rc   = (q & 1) * 8 + jc;       // col within 16-slice
    const int jg   = r_base + rc;            // global r
    const int lrow0 = gid * 16 + rrow;       // CTA-local batch row
    const int lrow1 = lrow0 + 8;
    const int brow0 = m_base + lrow0, brow1 = m_base + lrow1;

    const uint32_t b_lm = (uint32_t)(q * 8 + (lane & 7)) * B_ROW_BYTES
                        + (uint32_t)(lane >> 3) * 16;
    const uint32_t a_row_off = (uint32_t)(lane & 15) * A_ROW_BYTES + (uint32_t)(lane >> 4) * 16;
    const uint32_t tgA = (uint32_t)OFF_A + (uint32_t)tg * TG_BUFS;

    // reduction partner warp indices (same gid, same lane mapping)
    const int w_self = warp;
    const int w_h1 = gid * 8 + 4 + q;            // tier1, same h role
    const int w_z0 = gid * 8 + 0 + (q + 2);      // tier0 z role
    const int w_z1 = gid * 8 + 4 + (q + 2);      // tier1 z role

    volatile unsigned* flags = (volatile unsigned*)g_flags;

    float hold[2][2] = {};

    for (int t = 0; t < T_SZ; t++) {
        float xh[2][2], xz[2][2];
        if (gate_owner) {
            const float* sh_ = g_xh + (size_t)t * (B_SZ * R_SZ);
            const float* sz_ = g_xz + (size_t)t * (B_SZ * R_SZ);
            float2 a0 = __ldg((const float2*)(sh_ + (size_t)brow0 * R_SZ + jg));
            float2 a1 = __ldg((const float2*)(sh_ + (size_t)brow1 * R_SZ + jg));
            float2 c0 = __ldg((const float2*)(sz_ + (size_t)brow0 * R_SZ + jg));
            float2 c1 = __ldg((const float2*)(sz_ + (size_t)brow1 * R_SZ + jg));
            xh[0][0]=a0.x; xh[0][1]=a0.y; xh[1][0]=a1.x; xh[1][1]=a1.y;
            xz[0][0]=c0.x; xz[0][1]=c0.y; xz[1][0]=c1.x; xz[1][1]=c1.y;
        }

        const unsigned short* hhi = g_h_hi[t & 1];
        const unsigned short* hlo = g_h_lo[t & 1];

        float d0[4] = {0.f, 0.f, 0.f, 0.f};
        float d1[4] = {0.f, 0.f, 0.f, 0.f};

        // tier-group stages its chunk (16 rows x KC x 2 planes = 512 x 16B over 128 thr)
        auto stage = [&](int buf, int i) {
            const int kc = (2 * i + tier) * KC;
            #pragma unroll
            for (int r = 0; r < 4; r++) {
                int cid   = gtid + r * 128;
                int plane = cid >> 8;
                int rem   = cid & 255;
                int row   = rem >> 4;
                int c16   = rem & 15;
                uint32_t dA = sbase + tgA + (uint32_t)buf * (2 * TG_PLANE)
                            + (uint32_t)plane * TG_PLANE
                            + (uint32_t)row * A_ROW_BYTES + (uint32_t)c16 * 16;
                const unsigned short* sp = plane ? hlo : hhi;
                cp_async16(dA, sp + (size_t)(m_base + gid * 16 + row) * R_SZ + kc + c16 * 8);
            }
        };

        stage(0, 0);
        CP_COMMIT();
        for (int i = 0; i < NCHUNK / 2; i++) {
            if (i + 1 < NCHUNK / 2) { stage((i + 1) & 1, i + 1); CP_COMMIT(); CP_WAIT1(); }
            else                    { CP_WAIT0(); }
            BAR_SYNC(barid, 128);

            const int buf = i & 1;
            const int chunk = 2 * i + tier;
            const uint32_t a_hi_base = sbase + tgA + (uint32_t)buf * (2 * TG_PLANE);
            const uint32_t a_lo_base = a_hi_base + TG_PLANE;
            const uint32_t kB_chunk = (uint32_t)(chunk * KC) * 2;

            #pragma unroll
            for (int kb2 = 0; kb2 < KC / 32; kb2++) {
                const uint32_t kloc = (uint32_t)kb2 * 64;
                uint32_t ahA[4], ahB[4], alA[4], alB[4];
                ldsm_x4(ahA, a_hi_base + a_row_off + kloc);
                ldsm_x4(ahB, a_hi_base + a_row_off + kloc + 32);
                ldsm_x4(alA, a_lo_base + a_row_off + kloc);
                ldsm_x4(alB, a_lo_base + a_row_off + kloc + 32);

                uint32_t bh[4], bl[4];
                ldsm_x4(bh, sbase + OFF_BHI + b_lm + kB_chunk + kloc);
                ldsm_x4(bl, sbase + OFF_BLO + b_lm + kB_chunk + kloc);

                mma_bf16(d0, ahA, bh[0], bh[1]);
                mma_bf16(d1, ahB, bh[2], bh[3]);
                mma_bf16(d0, ahA, bl[0], bl[1]);
                mma_bf16(d1, ahB, bl[2], bl[3]);
                mma_bf16(d0, alA, bh[0], bh[1]);
                mma_bf16(d1, alB, bh[2], bh[3]);
            }
            BAR_SYNC(barid, 128);
        }

        // publish partial D
        float4 dq;
        dq.x = d0[0] + d1[0]; dq.y = d0[1] + d1[1];
        dq.z = d0[2] + d1[2]; dq.w = d0[3] + d1[3];
        redbuf[w_self * 32 + lane] = dq;
        __syncthreads();

        if (gate_owner) {
            float4 dh1 = redbuf[w_h1 * 32 + lane];
            float4 dz0 = redbuf[w_z0 * 32 + lane];
            float4 dz1 = redbuf[w_z1 * 32 + lane];
            float dh[4] = { dq.x + dh1.x, dq.y + dh1.y, dq.z + dh1.z, dq.w + dh1.w };
            float dz[4] = { dz0.x + dz1.x, dz0.y + dz1.y, dz0.z + dz1.z, dz0.w + dz1.w };

            unsigned short* dhi = g_h_hi[(t + 1) & 1];
            unsigned short* dlo = g_h_lo[(t + 1) & 1];
            #pragma unroll
            for (int qq = 0; qq < 2; qq++) {
                int br = (qq == 0) ? brow0 : brow1;
                uint32_t pk_hi, pk_lo;
                float hn[2];
                #pragma unroll
                for (int cc = 0; cc < 2; cc++) {
                    float pre_h = dh[qq * 2 + cc] + xh[qq][cc];
                    float pre_z = dz[qq * 2 + cc] + xz[qq][cc];
                    float z  = 1.0f / (1.0f + expf(-pre_z));
                    float hb = fmaxf(pre_h, 0.0f);
                    hn[cc] = z * hold[qq][cc] + (1.0f - z) * hb;
                    hold[qq][cc] = hn[cc];
                }
                pk_hi = pack2_hi(hn[0], hn[1]);
                pk_lo = pack2_lo(hn[0], hn[1]);
                size_t o = (size_t)br * R_SZ + jg;
                *(uint32_t*)(dhi + o) = pk_hi;
                *(uint32_t*)(dlo + o) = pk_lo;
                if (t == T_SZ - 1) {
                    g_hf[o] = hn[0]; g_hf[o + 1] = hn[1];
                }
            }
        }

        // all-poll-all grid barrier over 128 CTAs
        __threadfence();
        __syncthreads();
        if (tid == 0) flags[blockIdx.x * 32] = (unsigned)(t + 1);
        if (tid < NCTA) {
            while (flags[tid * 32] <= (unsigned)t) { }
        }
        __syncthreads();
    }
}

// ==================== Output: y = h_final @ Wy^T + by ====================
__global__ void __launch_bounds__(128) output_kernel(const float* __restrict__ Wy,
                                                     const float* __restrict__ by,
                                                     float* __restrict__ out) {
    __shared__ float shh[R_SZ];
    const int b = blockIdx.x;
    const int o = blockIdx.y * 128 + threadIdx.x;
    const float* hrow = g_hf + (size_t)b * R_SZ;
    #pragma unroll
    for (int v = 0; v < 2; v++) {
        int i4 = threadIdx.x + v * 128;
        ((float4*)shh)[i4] = *(const float4*)(hrow + i4 * 4);
    }
    __syncthreads();
    float acc = __ldg(&by[o]);
    const float* wrow = Wy + (size_t)o * R_SZ;
    #pragma unroll 8
    for (int k4 = 0; k4 < R_SZ / 4; k4++) {
        float4 h4 = ((const float4*)shh)[k4];
        float4 w4 = __ldg((const float4*)(wrow + k4 * 4));
        acc = fmaf(h4.x, w4.x, acc); acc = fmaf(h4.y, w4.y, acc);
        acc = fmaf(h4.z, w4.z, acc); acc = fmaf(h4.w, w4.w, acc);
    }
    out[(size_t)b * O_SZ + o] = acc;
}

// ==================== launch ====================
extern "C" void kernel_launch(void* const* d_in, const int* in_sizes, int n_in,
                              void* d_out, int out_size) {
    const float* x   = (const float*)d_in[0];
    const float* Wxh = (const float*)d_in[1];
    const float* bh  = (const float*)d_in[2];
    const float* Whh = (const float*)d_in[3];
    const float* Wxz = (const float*)d_in[4];
    const float* bz  = (const float*)d_in[5];
    const float* Whz = (const float*)d_in[6];
    const float* Wy  = (const float*)d_in[7];
    const float* by  = (const float*)d_in[8];
    float* out = (float*)d_out;

    static bool attr_set = false;
    if (!attr_set) {
        cudaFuncSetAttribute(scan_kernel,
                             cudaFuncAttributeMaxDynamicSharedMemorySize, SCAN_SMEM);
        cudaFuncSetAttribute(precompute_mma,
                             cudaFuncAttributeMaxDynamicSharedMemorySize, PP_SMEM);
        attr_set = true;
    }

    unsigned short *xhi_p, *xlo_p, *whi_p, *wlo_p;
    cudaGetSymbolAddress((void**)&xhi_p, g_x_hi);
    cudaGetSymbolAddress((void**)&xlo_p, g_x_lo);
    cudaGetSymbolAddress((void**)&whi_p, g_w_hi);
    cudaGetSymbolAddress((void**)&wlo_p, g_w_lo);
    split_kernel<<<(int)((size_t)M_SZ * D_SZ / 1024), 256>>>(x, xhi_p, xlo_p);
    split_kernel<<<(R_SZ * D_SZ) / 1024, 256>>>(Wxh, whi_p, wlo_p);
    split_kernel<<<(R_SZ * D_SZ) / 1024, 256>>>(Wxz, whi_p + (size_t)R_SZ * D_SZ,
                                                wlo_p + (size_t)R_SZ * D_SZ);

    precompute_mma<<<dim3(2048 / 128, M_SZ / 128), 512, PP_SMEM>>>(bh, bz);
    mz_kernel<<<dim3(R_SZ / 64, R_SZ / 64), 256>>>(Wxz, Whz);
    init_kernel<<<(B_SZ * R_SZ + 255) / 256, 256>>>();
    scan_kernel<<<NCTA, 512, SCAN_SMEM>>>(Whh);
    output_kernel<<<dim3(B_SZ, O_SZ / 128), 128>>>(Wy, by, out);
}

// round 13
// speedup vs baseline: 1.5984x; 1.0380x over previous
#include <cuda_runtime.h>
#include <cuda_bf16.h>
#include <cstdint>

// Problem dims
#define B_SZ 64
#define T_SZ 512
#define D_SZ 1024
#define R_SZ 1024
#define O_SZ 1024
#define M_SZ (B_SZ * T_SZ)   // 32768

// ---------------- device scratch (static: no runtime allocation) ----------------
__device__ float          g_xh[(size_t)T_SZ * B_SZ * R_SZ];   // [T][B][R]
__device__ float          g_xz[(size_t)T_SZ * B_SZ * R_SZ];   // [T][B][R]
__device__ float          g_Mz[(size_t)R_SZ * R_SZ];          // Wxz @ Whz
__device__ unsigned short g_x_hi[(size_t)M_SZ * D_SZ];        // X bf16 hi
__device__ unsigned short g_x_lo[(size_t)M_SZ * D_SZ];        // X bf16 lo
__device__ unsigned short g_w_hi[(size_t)2048 * D_SZ];        // [Wxh;Wxz] bf16 hi
__device__ unsigned short g_w_lo[(size_t)2048 * D_SZ];        // [Wxh;Wxz] bf16 lo
__device__ unsigned short g_h_hi[2][B_SZ * R_SZ];             // h bf16 hi (dbl buf)
__device__ unsigned short g_h_lo[2][B_SZ * R_SZ];             // h bf16 lo
__device__ float          g_hf[B_SZ * R_SZ];                  // final h fp32
__device__ unsigned       g_flags[128 * 32];                  // padded per-CTA step flags

// ==================== helpers ====================
__device__ __forceinline__ uint32_t smem_u32(const void* p) {
    uint32_t a;
    asm("{ .reg .u64 t; cvta.to.shared.u64 t, %1; cvt.u32.u64 %0, t; }" : "=r"(a) : "l"(p));
    return a;
}
__device__ __forceinline__ void ldsm_x4(uint32_t r[4], uint32_t addr) {
    asm volatile("ldmatrix.sync.aligned.m8n8.x4.shared.b16 {%0,%1,%2,%3}, [%4];"
                 : "=r"(r[0]), "=r"(r[1]), "=r"(r[2]), "=r"(r[3]) : "r"(addr));
}
__device__ __forceinline__ void mma_bf16(float d[4], const uint32_t a[4],
                                         uint32_t b0, uint32_t b1) {
    asm volatile("mma.sync.aligned.m16n8k16.row.col.f32.bf16.bf16.f32 "
                 "{%0,%1,%2,%3}, {%4,%5,%6,%7}, {%8,%9}, {%0,%1,%2,%3};"
                 : "+f"(d[0]), "+f"(d[1]), "+f"(d[2]), "+f"(d[3])
                 : "r"(a[0]), "r"(a[1]), "r"(a[2]), "r"(a[3]), "r"(b0), "r"(b1));
}
__device__ __forceinline__ void cp_async16(uint32_t dst, const void* src) {
    asm volatile("cp.async.cg.shared.global [%0], [%1], 16;" :: "r"(dst), "l"(src));
}
#define CP_COMMIT() asm volatile("cp.async.commit_group;" ::: "memory")
#define CP_WAIT0()  asm volatile("cp.async.wait_group 0;" ::: "memory")
#define BAR_SYNC(id, cnt) asm volatile("bar.sync %0, %1;" :: "r"(id), "r"(cnt) : "memory")

__device__ __forceinline__ uint32_t pack2_hi(float a, float b) {
    return (uint32_t)__bfloat16_as_ushort(__float2bfloat16_rn(a))
         | ((uint32_t)__bfloat16_as_ushort(__float2bfloat16_rn(b)) << 16);
}
__device__ __forceinline__ uint32_t pack2_lo(float a, float b) {
    float ra = a - __bfloat162float(__float2bfloat16_rn(a));
    float rb = b - __bfloat162float(__float2bfloat16_rn(b));
    return pack2_hi(ra, rb);
}

// ==================== init ====================
__global__ void init_kernel() {
    int i = blockIdx.x * blockDim.x + threadIdx.x;
    if (i < B_SZ * R_SZ) { g_h_hi[0][i] = 0; g_h_lo[0][i] = 0; }
    if (i < 128 * 32) g_flags[i] = 0u;
}

// ==================== fp32 -> bf16 hi/lo split ====================
__global__ void __launch_bounds__(256) split_kernel(const float* __restrict__ src,
                                                    unsigned short* __restrict__ hi,
                                                    unsigned short* __restrict__ lo) {
    size_t i = ((size_t)blockIdx.x * 256 + threadIdx.x) * 4;
    float4 v = *(const float4*)(src + i);
    uint2 h, l;
    h.x = pack2_hi(v.x, v.y); h.y = pack2_hi(v.z, v.w);
    l.x = pack2_lo(v.x, v.y); l.y = pack2_lo(v.z, v.w);
    *(uint2*)(hi + i) = h;
    *(uint2*)(lo + i) = l;
}

// ==================== Mz = Wxz @ Whz (SIMT fp32) ====================
__global__ void __launch_bounds__(256) mz_kernel(const float* __restrict__ Wxz,
                                                 const float* __restrict__ Whz) {
    __shared__ float As[16][68];
    __shared__ float Bs[16][68];
    const int tid = threadIdx.x;
    const int i0 = blockIdx.x * 64;
    const int j0 = blockIdx.y * 64;
    const int tx = tid & 15;
    const int ty = tid >> 4;
    float acc[4][4] = {};

    for (int k0 = 0; k0 < R_SZ; k0 += 16) {
        {
            int row = tid >> 2;
            int c4  = (tid & 3) * 4;
            float4 a = *(const float4*)(Wxz + (size_t)(i0 + row) * R_SZ + k0 + c4);
            As[c4 + 0][row] = a.x; As[c4 + 1][row] = a.y;
            As[c4 + 2][row] = a.z; As[c4 + 3][row] = a.w;
        }
        {
            int kk = tid >> 4;
            int j4 = (tid & 15) * 4;
            float4 b = *(const float4*)(Whz + (size_t)(k0 + kk) * R_SZ + j0 + j4);
            *(float4*)&Bs[kk][j4] = b;
        }
        __syncthreads();
        #pragma unroll
        for (int kk = 0; kk < 16; kk++) {
            float ar[4], br[4];
            *(float4*)ar = *(const float4*)&As[kk][ty * 4];
            *(float4*)br = *(const float4*)&Bs[kk][tx * 4];
            #pragma unroll
            for (int i = 0; i < 4; i++)
                #pragma unroll
                for (int j = 0; j < 4; j++)
                    acc[i][j] = fmaf(ar[i], br[j], acc[i][j]);
        }
        __syncthreads();
    }
    #pragma unroll
    for (int i = 0; i < 4; i++) {
        float4 v = make_float4(acc[i][0], acc[i][1], acc[i][2], acc[i][3]);
        *(float4*)(g_Mz + (size_t)(i0 + ty * 4 + i) * R_SZ + j0 + tx * 4) = v;
    }
}

// ==================== Precompute xh/xz: HMMA, ldmatrix B, single-sync pipeline ====================
// 128x128 tile, BK=32, 512 threads (16 warps = 4m x 4n), warp tile 32x32.
#define PP_ROW_B 80
#define PP_PLANE 10240
#define PP_SMEM (8 * PP_PLANE)

__global__ void __launch_bounds__(512, 1) precompute_mma(const float* __restrict__ bh_,
                                                         const float* __restrict__ bz_) {
    extern __shared__ char psm[];
    const uint32_t sb = smem_u32(psm);
    const int tid = threadIdx.x, warp = tid >> 5, lane = tid & 31;
    const long m_blk = (long)blockIdx.y * 128;
    const int  n_blk = blockIdx.x * 128;

    const float* bias; float* dst; int rb;
    if (n_blk < R_SZ) { bias = bh_; dst = g_xh; rb = n_blk; }
    else              { bias = bz_; dst = g_xz; rb = n_blk - R_SZ; }

    const int m0w = (warp & 3) * 32;
    const int n0w = (warp >> 2) * 32;

    float acc[2][4][4];
    #pragma unroll
    for (int a = 0; a < 2; a++)
        #pragma unroll
        for (int b = 0; b < 4; b++)
            #pragma unroll
            for (int c = 0; c < 4; c++) acc[a][b][c] = 0.0f;

    auto stage = [&](int buf, int k0) {
        int row = tid >> 2;
        int qt  = tid & 3;
        size_t sa = (size_t)(m_blk + row) * D_SZ + k0 + qt * 8;
        size_t sw = (size_t)(n_blk + row) * D_SZ + k0 + qt * 8;
        uint32_t o = (uint32_t)row * PP_ROW_B + (uint32_t)qt * 16;
        uint32_t base = sb + (uint32_t)(buf * 4) * PP_PLANE;
        cp_async16(base + o,                 g_x_hi + sa);
        cp_async16(base + PP_PLANE + o,      g_x_lo + sa);
        cp_async16(base + 2 * PP_PLANE + o,  g_w_hi + sw);
        cp_async16(base + 3 * PP_PLANE + o,  g_w_lo + sw);
    };

    // B frag ldmatrix address: row n0w+ni*8+(lane&7), 16B chunk lane>>3 (covers both k16s)
    const uint32_t b_lm_base = (uint32_t)(lane & 7) * PP_ROW_B + (uint32_t)(lane >> 3) * 16;
    const uint32_t a_lm_base = (uint32_t)(lane & 15) * PP_ROW_B + (uint32_t)(lane >> 4) * 16;

    int buf = 0;
    stage(0, 0);
    CP_COMMIT();
    for (int s = 0; s < D_SZ / 32; s++) {
        CP_WAIT0();
        __syncthreads();
        // stage(s+1) writes buf^1: its last readers (iter s-1) passed the barrier above
        if (s + 1 < D_SZ / 32) { stage(buf ^ 1, (s + 1) * 32); CP_COMMIT(); }

        const uint32_t AhS = sb + (uint32_t)((buf * 4 + 0) * PP_PLANE);
        const uint32_t AlS = AhS + PP_PLANE;
        const uint32_t BhS = sb + (uint32_t)((buf * 4 + 2) * PP_PLANE);
        const uint32_t BlS = BhS + PP_PLANE;

        uint32_t bh[4][4], bl[4][4];
        #pragma unroll
        for (int ni = 0; ni < 4; ni++) {
            uint32_t bo = (uint32_t)(n0w + ni * 8) * PP_ROW_B + b_lm_base;
            ldsm_x4(bh[ni], BhS + bo);
            ldsm_x4(bl[ni], BlS + bo);
        }
        #pragma unroll
        for (int k16 = 0; k16 < 2; k16++) {
            uint32_t ahi[2][4], alo[2][4];
            #pragma unroll
            for (int mi = 0; mi < 2; mi++) {
                uint32_t ar = (uint32_t)(m0w + mi * 16) * PP_ROW_B + a_lm_base
                            + (uint32_t)k16 * 32;
                ldsm_x4(ahi[mi], AhS + ar);
                ldsm_x4(alo[mi], AlS + ar);
            }
            #pragma unroll
            for (int mi = 0; mi < 2; mi++)
                #pragma unroll
                for (int ni = 0; ni < 4; ni++) {
                    mma_bf16(acc[mi][ni], ahi[mi], bh[ni][k16 * 2], bh[ni][k16 * 2 + 1]);
                    mma_bf16(acc[mi][ni], ahi[mi], bl[ni][k16 * 2], bl[ni][k16 * 2 + 1]);
                    mma_bf16(acc[mi][ni], alo[mi], bh[ni][k16 * 2], bh[ni][k16 * 2 + 1]);
                }
        }
        buf ^= 1;
    }

    #pragma unroll
    for (int ni = 0; ni < 4; ni++) {
        int col = n0w + ni * 8 + (lane & 3) * 2;
        float2 bv = *(const float2*)(bias + rb + col);
        #pragma unroll
        for (int mi = 0; mi < 2; mi++) {
            #pragma unroll
            for (int half = 0; half < 2; half++) {
                long m = m_blk + m0w + mi * 16 + (lane >> 2) + half * 8;
                int b = (int)(m >> 9), t = (int)(m & 511);
                float2 v;
                v.x = acc[mi][ni][half * 2 + 0] + bv.x;
                v.y = acc[mi][ni][half * 2 + 1] + bv.y;
                *(float2*)(dst + ((long)t * B_SZ + b) * R_SZ + rb + col) = v;
            }
        }
    }
}

// ==================== Persistent scan: 128 CTAs, 512 thr, K-split tiers, 1 bar/iter ====================
// CTA c: batch rows [32*(c&1), +32), r-slice [(c>>1)*16, +16).
// 16 warps = 2 m-groups (gid) x 2 K-tiers x 4 roles (q: 0,1 h / 2,3 z).
// Tier-group tg (128 thr) owns chunks c ≡ tier (mod 2), private double-buffered A,
// single named barrier per iter (stage(next) issued after barrier -> safe reuse).
#define NCTA 128
#define KC 128
#define NCHUNK (R_SZ / KC)                   // 8 total, 4 per tier
#define B_ROW_BYTES 2064                     // (1024+8) bf16
#define A_ROW_BYTES 272                      // (128+8) bf16
#define TG_PLANE (16 * A_ROW_BYTES)          // 4352
#define TG_BUFS (4 * TG_PLANE)               // 17408 [buf0 hi, buf0 lo, buf1 hi, buf1 lo]
#define OFF_BHI 0
#define OFF_BLO (32 * B_ROW_BYTES)           // 66048
#define OFF_A   (2 * 32 * B_ROW_BYTES)       // 132096
#define OFF_RED (OFF_A + 4 * TG_BUFS)        // 201728
#define SCAN_SMEM (OFF_RED + 16 * 32 * 16)   // 209920

__global__ void __launch_bounds__(512) scan_kernel(const float* __restrict__ Whh) {
    extern __shared__ char smem[];
    const uint32_t sbase = smem_u32(smem);
    float4* redbuf = (float4*)(smem + OFF_RED);
    const int tid  = threadIdx.x;
    const int warp = tid >> 5;
    const int lane = tid & 31;
    const int gid  = warp >> 3;              // m-stripe group 0..1
    const int tier = (warp >> 2) & 1;        // K-tier 0..1
    const int q    = warp & 3;               // role: 0,1 h; 2,3 z
    const int tg   = warp >> 2;              // tier-group 0..3
    const int gtid = tid & 127;
    const int barid = 1 + tg;
    const int m_base = (blockIdx.x & 1) * 32;
    const int r_base = (blockIdx.x >> 1) * 16;

    for (int i = tid; i < 32 * R_SZ; i += 512) {
        int j = i >> 10;
        int k = i & 1023;
        float w = (j < 16) ? Whh[(size_t)(r_base + j) * R_SZ + k]
                           : g_Mz[(size_t)(r_base + j - 16) * R_SZ + k];
        __nv_bfloat16 h = __float2bfloat16_rn(w);
        __nv_bfloat16 l = __float2bfloat16_rn(w - __bfloat162float(h));
        *(unsigned short*)(smem + OFF_BHI + j * B_ROW_BYTES + k * 2) = __bfloat16_as_ushort(h);
        *(unsigned short*)(smem + OFF_BLO + j * B_ROW_BYTES + k * 2) = __bfloat16_as_ushort(l);
    }
    __syncthreads();

    const bool is_h = (q < 2);
    const bool gate_owner = (tier == 0) && is_h;

    const int rrow = lane >> 2;
    const int jc   = (lane & 3) * 2;
    const int rc   = (q & 1) * 8 + jc;
    const int jg   = r_base + rc;
    const int lrow0 = gid * 16 + rrow;
    const int lrow1 = lrow0 + 8;
    const int brow0 = m_base + lrow0, brow1 = m_base + lrow1;

    const uint32_t b_lm = (uint32_t)(q * 8 + (lane & 7)) * B_ROW_BYTES
                        + (uint32_t)(lane >> 3) * 16;
    const uint32_t a_row_off = (uint32_t)(lane & 15) * A_ROW_BYTES + (uint32_t)(lane >> 4) * 16;
    const uint32_t tgA = (uint32_t)OFF_A + (uint32_t)tg * TG_BUFS;

    const int w_self = warp;
    const int w_h1 = gid * 8 + 4 + q;
    const int w_z0 = gid * 8 + 0 + (q + 2);
    const int w_z1 = gid * 8 + 4 + (q + 2);

    volatile unsigned* flags = (volatile unsigned*)g_flags;

    float hold[2][2] = {};

    for (int t = 0; t < T_SZ; t++) {
        float xh[2][2], xz[2][2];
        if (gate_owner) {
            const float* sh_ = g_xh + (size_t)t * (B_SZ * R_SZ);
            const float* sz_ = g_xz + (size_t)t * (B_SZ * R_SZ);
            float2 a0 = __ldg((const float2*)(sh_ + (size_t)brow0 * R_SZ + jg));
            float2 a1 = __ldg((const float2*)(sh_ + (size_t)brow1 * R_SZ + jg));
            float2 c0 = __ldg((const float2*)(sz_ + (size_t)brow0 * R_SZ + jg));
            float2 c1 = __ldg((const float2*)(sz_ + (size_t)brow1 * R_SZ + jg));
            xh[0][0]=a0.x; xh[0][1]=a0.y; xh[1][0]=a1.x; xh[1][1]=a1.y;
            xz[0][0]=c0.x; xz[0][1]=c0.y; xz[1][0]=c1.x; xz[1][1]=c1.y;
        }

        const unsigned short* hhi = g_h_hi[t & 1];
        const unsigned short* hlo = g_h_lo[t & 1];

        float d0[4] = {0.f, 0.f, 0.f, 0.f};
        float d1[4] = {0.f, 0.f, 0.f, 0.f};

        auto stage = [&](int buf, int i) {
            const int kc = (2 * i + tier) * KC;
            #pragma unroll
            for (int r = 0; r < 4; r++) {
                int cid   = gtid + r * 128;
                int plane = cid >> 8;
                int rem   = cid & 255;
                int row   = rem >> 4;
                int c16   = rem & 15;
                uint32_t dA = sbase + tgA + (uint32_t)buf * (2 * TG_PLANE)
                            + (uint32_t)plane * TG_PLANE
                            + (uint32_t)row * A_ROW_BYTES + (uint32_t)c16 * 16;
                const unsigned short* sp = plane ? hlo : hhi;
                cp_async16(dA, sp + (size_t)(m_base + gid * 16 + row) * R_SZ + kc + c16 * 8);
            }
        };

        stage(0, 0);
        CP_COMMIT();
        for (int i = 0; i < NCHUNK / 2; i++) {
            CP_WAIT0();
            BAR_SYNC(barid, 128);
            // stage(i+1) writes buf^1: readers from iter i-1 have passed the barrier
            if (i + 1 < NCHUNK / 2) { stage((i + 1) & 1, i + 1); CP_COMMIT(); }

            const int buf = i & 1;
            const int chunk = 2 * i + tier;
            const uint32_t a_hi_base = sbase + tgA + (uint32_t)buf * (2 * TG_PLANE);
            const uint32_t a_lo_base = a_hi_base + TG_PLANE;
            const uint32_t kB_chunk = (uint32_t)(chunk * KC) * 2;

            #pragma unroll
            for (int kb2 = 0; kb2 < KC / 32; kb2++) {
                const uint32_t kloc = (uint32_t)kb2 * 64;
                uint32_t ahA[4], ahB[4], alA[4], alB[4];
                ldsm_x4(ahA, a_hi_base + a_row_off + kloc);
                ldsm_x4(ahB, a_hi_base + a_row_off + kloc + 32);
                ldsm_x4(alA, a_lo_base + a_row_off + kloc);
                ldsm_x4(alB, a_lo_base + a_row_off + kloc + 32);

                uint32_t bh[4], bl[4];
                ldsm_x4(bh, sbase + OFF_BHI + b_lm + kB_chunk + kloc);
                ldsm_x4(bl, sbase + OFF_BLO + b_lm + kB_chunk + kloc);

                mma_bf16(d0, ahA, bh[0], bh[1]);
                mma_bf16(d1, ahB, bh[2], bh[3]);
                mma_bf16(d0, ahA, bl[0], bl[1]);
                mma_bf16(d1, ahB, bl[2], bl[3]);
                mma_bf16(d0, alA, bh[0], bh[1]);
                mma_bf16(d1, alB, bh[2], bh[3]);
            }
        }

        float4 dq;
        dq.x = d0[0] + d1[0]; dq.y = d0[1] + d1[1];
        dq.z = d0[2] + d1[2]; dq.w = d0[3] + d1[3];
        redbuf[w_self * 32 + lane] = dq;
        __syncthreads();

        if (gate_owner) {
            float4 dh1 = redbuf[w_h1 * 32 + lane];
            float4 dz0 = redbuf[w_z0 * 32 + lane];
            float4 dz1 = redbuf[w_z1 * 32 + lane];
            float dh[4] = { dq.x + dh1.x, dq.y + dh1.y, dq.z + dh1.z, dq.w + dh1.w };
            float dz[4] = { dz0.x + dz1.x, dz0.y + dz1.y, dz0.z + dz1.z, dz0.w + dz1.w };

            unsigned short* dhi = g_h_hi[(t + 1) & 1];
            unsigned short* dlo = g_h_lo[(t + 1) & 1];
            #pragma unroll
            for (int qq = 0; qq < 2; qq++) {
                int br = (qq == 0) ? brow0 : brow1;
                float hn[2];
                #pragma unroll
                for (int cc = 0; cc < 2; cc++) {
                    float pre_h = dh[qq * 2 + cc] + xh[qq][cc];
                    float pre_z = dz[qq * 2 + cc] + xz[qq][cc];
                    float z  = 1.0f / (1.0f + expf(-pre_z));
                    float hb = fmaxf(pre_h, 0.0f);
                    hn[cc] = z * hold[qq][cc] + (1.0f - z) * hb;
                    hold[qq][cc] = hn[cc];
                }
                size_t o = (size_t)br * R_SZ + jg;
                *(uint32_t*)(dhi + o) = pack2_hi(hn[0], hn[1]);
                *(uint32_t*)(dlo + o) = pack2_lo(hn[0], hn[1]);
                if (t == T_SZ - 1) {
                    g_hf[o] = hn[0]; g_hf[o + 1] = hn[1];
                }
            }
        }

        // all-poll-all grid barrier over 128 CTAs
        __threadfence();
        __syncthreads();
        if (tid == 0) flags[blockIdx.x * 32] = (unsigned)(t + 1);
        if (tid < NCTA) {
            while (flags[tid * 32] <= (unsigned)t) { }
        }
        __syncthreads();
    }
}

// ==================== Output: y = h_final @ Wy^T + by ====================
__global__ void __launch_bounds__(128) output_kernel(const float* __restrict__ Wy,
                                                     const float* __restrict__ by,
                                                     float* __restrict__ out) {
    __shared__ float shh[R_SZ];
    const int b = blockIdx.x;
    const int o = blockIdx.y * 128 + threadIdx.x;
    const float* hrow = g_hf + (size_t)b * R_SZ;
    #pragma unroll
    for (int v = 0; v < 2; v++) {
        int i4 = threadIdx.x + v * 128;
        ((float4*)shh)[i4] = *(const float4*)(hrow + i4 * 4);
    }
    __syncthreads();
    float acc = __ldg(&by[o]);
    const float* wrow = Wy + (size_t)o * R_SZ;
    #pragma unroll 8
    for (int k4 = 0; k4 < R_SZ / 4; k4++) {
        float4 h4 = ((const float4*)shh)[k4];
        float4 w4 = __ldg((const float4*)(wrow + k4 * 4));
        acc = fmaf(h4.x, w4.x, acc); acc = fmaf(h4.y, w4.y, acc);
        acc = fmaf(h4.z, w4.z, acc); acc = fmaf(h4.w, w4.w, acc);
    }
    out[(size_t)b * O_SZ + o] = acc;
}

// ==================== launch ====================
extern "C" void kernel_launch(void* const* d_in, const int* in_sizes, int n_in,
                              void* d_out, int out_size) {
    const float* x   = (const float*)d_in[0];
    const float* Wxh = (const float*)d_in[1];
    const float* bh  = (const float*)d_in[2];
    const float* Whh = (const float*)d_in[3];
    const float* Wxz = (const float*)d_in[4];
    const float* bz  = (const float*)d_in[5];
    const float* Whz = (const float*)d_in[6];
    const float* Wy  = (const float*)d_in[7];
    const float* by  = (const float*)d_in[8];
    float* out = (float*)d_out;

    static bool attr_set = false;
    if (!attr_set) {
        cudaFuncSetAttribute(scan_kernel,
                             cudaFuncAttributeMaxDynamicSharedMemorySize, SCAN_SMEM);
        cudaFuncSetAttribute(precompute_mma,
                             cudaFuncAttributeMaxDynamicSharedMemorySize, PP_SMEM);
        attr_set = true;
    }

    unsigned short *xhi_p, *xlo_p, *whi_p, *wlo_p;
    cudaGetSymbolAddress((void**)&xhi_p, g_x_hi);
    cudaGetSymbolAddress((void**)&xlo_p, g_x_lo);
    cudaGetSymbolAddress((void**)&whi_p, g_w_hi);
    cudaGetSymbolAddress((void**)&wlo_p, g_w_lo);
    split_kernel<<<(int)((size_t)M_SZ * D_SZ / 1024), 256>>>(x, xhi_p, xlo_p);
    split_kernel<<<(R_SZ * D_SZ) / 1024, 256>>>(Wxh, whi_p, wlo_p);
    split_kernel<<<(R_SZ * D_SZ) / 1024, 256>>>(Wxz, whi_p + (size_t)R_SZ * D_SZ,
                                                wlo_p + (size_t)R_SZ * D_SZ);

    precompute_mma<<<dim3(2048 / 128, M_SZ / 128), 512, PP_SMEM>>>(bh, bz);
    mz_kernel<<<dim3(R_SZ / 64, R_SZ / 64), 256>>>(Wxz, Whz);
    init_kernel<<<(B_SZ * R_SZ + 255) / 256, 256>>>();
    scan_kernel<<<NCTA, 512, SCAN_SMEM>>>(Whh);
    output_kernel<<<dim3(B_SZ, O_SZ / 128), 128>>>(Wy, by, out);
}

// round 14
// speedup vs baseline: 1.6851x; 1.0542x over previous
#include <cuda_runtime.h>
#include <cuda_bf16.h>
#include <cstdint>

// Problem dims
#define B_SZ 64
#define T_SZ 512
#define D_SZ 1024
#define R_SZ 1024
#define O_SZ 1024
#define M_SZ (B_SZ * T_SZ)   // 32768

// ---------------- device scratch (static: no runtime allocation) ----------------
__device__ float          g_xh[(size_t)T_SZ * B_SZ * R_SZ];   // [T][B][R]
__device__ float          g_xz[(size_t)T_SZ * B_SZ * R_SZ];   // [T][B][R]
__device__ float          g_Mz[(size_t)R_SZ * R_SZ];          // Wxz @ Whz
__device__ unsigned short g_x_hi[(size_t)M_SZ * D_SZ];        // X bf16 hi
__device__ unsigned short g_x_lo[(size_t)M_SZ * D_SZ];        // X bf16 lo
__device__ unsigned short g_w_hi[(size_t)2048 * D_SZ];        // [Wxh;Wxz] bf16 hi
__device__ unsigned short g_w_lo[(size_t)2048 * D_SZ];        // [Wxh;Wxz] bf16 lo
__device__ unsigned short g_h_hi[2][B_SZ * R_SZ];             // h bf16 hi (dbl buf)
__device__ unsigned short g_h_lo[2][B_SZ * R_SZ];             // h bf16 lo
__device__ float          g_hf[B_SZ * R_SZ];                  // final h fp32
__device__ unsigned       g_flags[128 * 32];                  // padded per-CTA step flags

// ==================== helpers ====================
__device__ __forceinline__ uint32_t smem_u32(const void* p) {
    uint32_t a;
    asm("{ .reg .u64 t; cvta.to.shared.u64 t, %1; cvt.u32.u64 %0, t; }" : "=r"(a) : "l"(p));
    return a;
}
__device__ __forceinline__ void ldsm_x4(uint32_t r[4], uint32_t addr) {
    asm volatile("ldmatrix.sync.aligned.m8n8.x4.shared.b16 {%0,%1,%2,%3}, [%4];"
                 : "=r"(r[0]), "=r"(r[1]), "=r"(r[2]), "=r"(r[3]) : "r"(addr));
}
__device__ __forceinline__ void mma_bf16(float d[4], const uint32_t a[4],
                                         uint32_t b0, uint32_t b1) {
    asm volatile("mma.sync.aligned.m16n8k16.row.col.f32.bf16.bf16.f32 "
                 "{%0,%1,%2,%3}, {%4,%5,%6,%7}, {%8,%9}, {%0,%1,%2,%3};"
                 : "+f"(d[0]), "+f"(d[1]), "+f"(d[2]), "+f"(d[3])
                 : "r"(a[0]), "r"(a[1]), "r"(a[2]), "r"(a[3]), "r"(b0), "r"(b1));
}
__device__ __forceinline__ void cp_async16(uint32_t dst, const void* src) {
    asm volatile("cp.async.cg.shared.global [%0], [%1], 16;" :: "r"(dst), "l"(src));
}
#define CP_COMMIT() asm volatile("cp.async.commit_group;" ::: "memory")
#define CP_WAIT0()  asm volatile("cp.async.wait_group 0;" ::: "memory")
#define BAR_SYNC(id, cnt) asm volatile("bar.sync %0, %1;" :: "r"(id), "r"(cnt) : "memory")

__device__ __forceinline__ uint32_t pack2_hi(float a, float b) {
    return (uint32_t)__bfloat16_as_ushort(__float2bfloat16_rn(a))
         | ((uint32_t)__bfloat16_as_ushort(__float2bfloat16_rn(b)) << 16);
}
__device__ __forceinline__ uint32_t pack2_lo(float a, float b) {
    float ra = a - __bfloat162float(__float2bfloat16_rn(a));
    float rb = b - __bfloat162float(__float2bfloat16_rn(b));
    return pack2_hi(ra, rb);
}

// ==================== init ====================
__global__ void init_kernel() {
    int i = blockIdx.x * blockDim.x + threadIdx.x;
    if (i < B_SZ * R_SZ) { g_h_hi[0][i] = 0; g_h_lo[0][i] = 0; }
    if (i < 128 * 32) g_flags[i] = 0u;
}

// ==================== fp32 -> bf16 hi/lo split ====================
__global__ void __launch_bounds__(256) split_kernel(const float* __restrict__ src,
                                                    unsigned short* __restrict__ hi,
                                                    unsigned short* __restrict__ lo) {
    size_t i = ((size_t)blockIdx.x * 256 + threadIdx.x) * 4;
    float4 v = *(const float4*)(src + i);
    uint2 h, l;
    h.x = pack2_hi(v.x, v.y); h.y = pack2_hi(v.z, v.w);
    l.x = pack2_lo(v.x, v.y); l.y = pack2_lo(v.z, v.w);
    *(uint2*)(hi + i) = h;
    *(uint2*)(lo + i) = l;
}

// ==================== Mz = Wxz @ Whz (SIMT fp32) ====================
__global__ void __launch_bounds__(256) mz_kernel(const float* __restrict__ Wxz,
                                                 const float* __restrict__ Whz) {
    __shared__ float As[16][68];
    __shared__ float Bs[16][68];
    const int tid = threadIdx.x;
    const int i0 = blockIdx.x * 64;
    const int j0 = blockIdx.y * 64;
    const int tx = tid & 15;
    const int ty = tid >> 4;
    float acc[4][4] = {};

    for (int k0 = 0; k0 < R_SZ; k0 += 16) {
        {
            int row = tid >> 2;
            int c4  = (tid & 3) * 4;
            float4 a = *(const float4*)(Wxz + (size_t)(i0 + row) * R_SZ + k0 + c4);
            As[c4 + 0][row] = a.x; As[c4 + 1][row] = a.y;
            As[c4 + 2][row] = a.z; As[c4 + 3][row] = a.w;
        }
        {
            int kk = tid >> 4;
            int j4 = (tid & 15) * 4;
            float4 b = *(const float4*)(Whz + (size_t)(k0 + kk) * R_SZ + j0 + j4);
            *(float4*)&Bs[kk][j4] = b;
        }
        __syncthreads();
        #pragma unroll
        for (int kk = 0; kk < 16; kk++) {
            float ar[4], br[4];
            *(float4*)ar = *(const float4*)&As[kk][ty * 4];
            *(float4*)br = *(const float4*)&Bs[kk][tx * 4];
            #pragma unroll
            for (int i = 0; i < 4; i++)
                #pragma unroll
                for (int j = 0; j < 4; j++)
                    acc[i][j] = fmaf(ar[i], br[j], acc[i][j]);
        }
        __syncthreads();
    }
    #pragma unroll
    for (int i = 0; i < 4; i++) {
        float4 v = make_float4(acc[i][0], acc[i][1], acc[i][2], acc[i][3]);
        *(float4*)(g_Mz + (size_t)(i0 + ty * 4 + i) * R_SZ + j0 + tx * 4) = v;
    }
}

// ==================== Precompute xh/xz: HMMA, BK=64, ldmatrix B, single-sync ====================
// 128x128 tile, BK=64, 512 threads (16 warps = 4m x 4n), warp tile 32x32.
#define PP_ROW_B 144                         // (64+8) bf16
#define PP_PLANE 18432                       // 128 rows * 144
#define PP_SMEM (8 * PP_PLANE)               // 147456

__global__ void __launch_bounds__(512, 1) precompute_mma(const float* __restrict__ bh_,
                                                         const float* __restrict__ bz_) {
    extern __shared__ char psm[];
    const uint32_t sb = smem_u32(psm);
    const int tid = threadIdx.x, warp = tid >> 5, lane = tid & 31;
    const long m_blk = (long)blockIdx.y * 128;
    const int  n_blk = blockIdx.x * 128;

    const float* bias; float* dst; int rb;
    if (n_blk < R_SZ) { bias = bh_; dst = g_xh; rb = n_blk; }
    else              { bias = bz_; dst = g_xz; rb = n_blk - R_SZ; }

    const int m0w = (warp & 3) * 32;
    const int n0w = (warp >> 2) * 32;

    float acc[2][4][4];
    #pragma unroll
    for (int a = 0; a < 2; a++)
        #pragma unroll
        for (int b = 0; b < 4; b++)
            #pragma unroll
            for (int c = 0; c < 4; c++) acc[a][b][c] = 0.0f;

    // stage one 64-wide K slab: 4 planes x 128 rows x 128B = 4096 x 16B over 512 thr
    auto stage = [&](int buf, int k0) {
        #pragma unroll
        for (int r = 0; r < 2; r++) {
            int item = tid + r * 512;            // 0..1023 per plane-pair index
            int row  = item >> 3;                // 0..127
            int c8   = item & 7;                 // 16B chunk within 128B row
            size_t sa = (size_t)(m_blk + row) * D_SZ + k0 + c8 * 8;
            size_t sw = (size_t)(n_blk + row) * D_SZ + k0 + c8 * 8;
            uint32_t o = (uint32_t)row * PP_ROW_B + (uint32_t)c8 * 16;
            uint32_t base = sb + (uint32_t)(buf * 4) * PP_PLANE;
            cp_async16(base + o,                g_x_hi + sa);
            cp_async16(base + PP_PLANE + o,     g_x_lo + sa);
            cp_async16(base + 2 * PP_PLANE + o, g_w_hi + sw);
            cp_async16(base + 3 * PP_PLANE + o, g_w_lo + sw);
        }
    };

    const uint32_t b_lm_base = (uint32_t)(lane & 7) * PP_ROW_B + (uint32_t)(lane >> 3) * 16;
    const uint32_t a_lm_base = (uint32_t)(lane & 15) * PP_ROW_B + (uint32_t)(lane >> 4) * 16;

    int buf = 0;
    stage(0, 0);
    CP_COMMIT();
    for (int s = 0; s < D_SZ / 64; s++) {
        CP_WAIT0();
        __syncthreads();
        if (s + 1 < D_SZ / 64) { stage(buf ^ 1, (s + 1) * 64); CP_COMMIT(); }

        const uint32_t AhS = sb + (uint32_t)((buf * 4 + 0) * PP_PLANE);
        const uint32_t AlS = AhS + PP_PLANE;
        const uint32_t BhS = sb + (uint32_t)((buf * 4 + 2) * PP_PLANE);
        const uint32_t BlS = BhS + PP_PLANE;

        #pragma unroll
        for (int k32 = 0; k32 < 2; k32++) {
            uint32_t bh[4][4], bl[4][4];
            #pragma unroll
            for (int ni = 0; ni < 4; ni++) {
                uint32_t bo = (uint32_t)(n0w + ni * 8) * PP_ROW_B + b_lm_base
                            + (uint32_t)k32 * 64;
                ldsm_x4(bh[ni], BhS + bo);
                ldsm_x4(bl[ni], BlS + bo);
            }
            #pragma unroll
            for (int k16 = 0; k16 < 2; k16++) {
                uint32_t ahi[2][4], alo[2][4];
                #pragma unroll
                for (int mi = 0; mi < 2; mi++) {
                    uint32_t ar = (uint32_t)(m0w + mi * 16) * PP_ROW_B + a_lm_base
                                + (uint32_t)k32 * 64 + (uint32_t)k16 * 32;
                    ldsm_x4(ahi[mi], AhS + ar);
                    ldsm_x4(alo[mi], AlS + ar);
                }
                #pragma unroll
                for (int mi = 0; mi < 2; mi++)
                    #pragma unroll
                    for (int ni = 0; ni < 4; ni++) {
                        mma_bf16(acc[mi][ni], ahi[mi], bh[ni][k16 * 2], bh[ni][k16 * 2 + 1]);
                        mma_bf16(acc[mi][ni], ahi[mi], bl[ni][k16 * 2], bl[ni][k16 * 2 + 1]);
                        mma_bf16(acc[mi][ni], alo[mi], bh[ni][k16 * 2], bh[ni][k16 * 2 + 1]);
                    }
            }
        }
        buf ^= 1;
    }

    #pragma unroll
    for (int ni = 0; ni < 4; ni++) {
        int col = n0w + ni * 8 + (lane & 3) * 2;
        float2 bv = *(const float2*)(bias + rb + col);
        #pragma unroll
        for (int mi = 0; mi < 2; mi++) {
            #pragma unroll
            for (int half = 0; half < 2; half++) {
                long m = m_blk + m0w + mi * 16 + (lane >> 2) + half * 8;
                int b = (int)(m >> 9), t = (int)(m & 511);
                float2 v;
                v.x = acc[mi][ni][half * 2 + 0] + bv.x;
                v.y = acc[mi][ni][half * 2 + 1] + bv.y;
                *(float2*)(dst + ((long)t * B_SZ + b) * R_SZ + rb + col) = v;
            }
        }
    }
}

// ==================== Persistent scan: 128 CTAs, K-split tiers, per-half barrier ====================
// CTA c: batch half c&1 (rows [32*(c&1), +32)), r-slice [(c>>1)*16, +16).
// 16 warps = 2 m-groups (gid) x 2 K-tiers x 4 roles (q). Tier-group tg (128 thr)
// owns chunks ≡ tier (mod 2), private dbl-buffered A, 1 named barrier/iter.
// Grid barrier: two independent 64-CTA domains (one per batch half).
#define NCTA 128
#define KC 128
#define NCHUNK (R_SZ / KC)                   // 8 total, 4 per tier
#define B_ROW_BYTES 2064                     // (1024+8) bf16
#define A_ROW_BYTES 272                      // (128+8) bf16
#define TG_PLANE (16 * A_ROW_BYTES)          // 4352
#define TG_BUFS (4 * TG_PLANE)               // 17408
#define OFF_BHI 0
#define OFF_BLO (32 * B_ROW_BYTES)           // 66048
#define OFF_A   (2 * 32 * B_ROW_BYTES)       // 132096
#define OFF_RED (OFF_A + 4 * TG_BUFS)        // 201728
#define SCAN_SMEM (OFF_RED + 16 * 32 * 16)   // 209920

__global__ void __launch_bounds__(512) scan_kernel(const float* __restrict__ Whh) {
    extern __shared__ char smem[];
    const uint32_t sbase = smem_u32(smem);
    float4* redbuf = (float4*)(smem + OFF_RED);
    const int tid  = threadIdx.x;
    const int warp = tid >> 5;
    const int lane = tid & 31;
    const int gid  = warp >> 3;
    const int tier = (warp >> 2) & 1;
    const int q    = warp & 3;
    const int tg   = warp >> 2;
    const int gtid = tid & 127;
    const int barid = 1 + tg;
    const int half   = blockIdx.x & 1;
    const int m_base = half * 32;
    const int r_base = (blockIdx.x >> 1) * 16;

    for (int i = tid; i < 32 * R_SZ; i += 512) {
        int j = i >> 10;
        int k = i & 1023;
        float w = (j < 16) ? Whh[(size_t)(r_base + j) * R_SZ + k]
                           : g_Mz[(size_t)(r_base + j - 16) * R_SZ + k];
        __nv_bfloat16 h = __float2bfloat16_rn(w);
        __nv_bfloat16 l = __float2bfloat16_rn(w - __bfloat162float(h));
        *(unsigned short*)(smem + OFF_BHI + j * B_ROW_BYTES + k * 2) = __bfloat16_as_ushort(h);
        *(unsigned short*)(smem + OFF_BLO + j * B_ROW_BYTES + k * 2) = __bfloat16_as_ushort(l);
    }
    __syncthreads();

    const bool is_h = (q < 2);
    const bool gate_owner = (tier == 0) && is_h;

    const int rrow = lane >> 2;
    const int jc   = (lane & 3) * 2;
    const int rc   = (q & 1) * 8 + jc;
    const int jg   = r_base + rc;
    const int lrow0 = gid * 16 + rrow;
    const int lrow1 = lrow0 + 8;
    const int brow0 = m_base + lrow0, brow1 = m_base + lrow1;

    const uint32_t b_lm = (uint32_t)(q * 8 + (lane & 7)) * B_ROW_BYTES
                        + (uint32_t)(lane >> 3) * 16;
    const uint32_t a_row_off = (uint32_t)(lane & 15) * A_ROW_BYTES + (uint32_t)(lane >> 4) * 16;
    const uint32_t tgA = (uint32_t)OFF_A + (uint32_t)tg * TG_BUFS;

    const int w_self = warp;
    const int w_h1 = gid * 8 + 4 + q;
    const int w_z0 = gid * 8 + 0 + (q + 2);
    const int w_z1 = gid * 8 + 4 + (q + 2);

    volatile unsigned* flags = (volatile unsigned*)g_flags;

    float hold[2][2] = {};

    for (int t = 0; t < T_SZ; t++) {
        float xh[2][2], xz[2][2];
        if (gate_owner) {
            const float* sh_ = g_xh + (size_t)t * (B_SZ * R_SZ);
            const float* sz_ = g_xz + (size_t)t * (B_SZ * R_SZ);
            float2 a0 = __ldg((const float2*)(sh_ + (size_t)brow0 * R_SZ + jg));
            float2 a1 = __ldg((const float2*)(sh_ + (size_t)brow1 * R_SZ + jg));
            float2 c0 = __ldg((const float2*)(sz_ + (size_t)brow0 * R_SZ + jg));
            float2 c1 = __ldg((const float2*)(sz_ + (size_t)brow1 * R_SZ + jg));
            xh[0][0]=a0.x; xh[0][1]=a0.y; xh[1][0]=a1.x; xh[1][1]=a1.y;
            xz[0][0]=c0.x; xz[0][1]=c0.y; xz[1][0]=c1.x; xz[1][1]=c1.y;
        }

        const unsigned short* hhi = g_h_hi[t & 1];
        const unsigned short* hlo = g_h_lo[t & 1];

        float d0[4] = {0.f, 0.f, 0.f, 0.f};
        float d1[4] = {0.f, 0.f, 0.f, 0.f};

        auto stage = [&](int buf, int i) {
            const int kc = (2 * i + tier) * KC;
            #pragma unroll
            for (int r = 0; r < 4; r++) {
                int cid   = gtid + r * 128;
                int plane = cid >> 8;
                int rem   = cid & 255;
                int row   = rem >> 4;
                int c16   = rem & 15;
                uint32_t dA = sbase + tgA + (uint32_t)buf * (2 * TG_PLANE)
                            + (uint32_t)plane * TG_PLANE
                            + (uint32_t)row * A_ROW_BYTES + (uint32_t)c16 * 16;
                const unsigned short* sp = plane ? hlo : hhi;
                cp_async16(dA, sp + (size_t)(m_base + gid * 16 + row) * R_SZ + kc + c16 * 8);
            }
        };

        stage(0, 0);
        CP_COMMIT();
        for (int i = 0; i < NCHUNK / 2; i++) {
            CP_WAIT0();
            BAR_SYNC(barid, 128);
            if (i + 1 < NCHUNK / 2) { stage((i + 1) & 1, i + 1); CP_COMMIT(); }

            const int buf = i & 1;
            const int chunk = 2 * i + tier;
            const uint32_t a_hi_base = sbase + tgA + (uint32_t)buf * (2 * TG_PLANE);
            const uint32_t a_lo_base = a_hi_base + TG_PLANE;
            const uint32_t kB_chunk = (uint32_t)(chunk * KC) * 2;

            #pragma unroll
            for (int kb2 = 0; kb2 < KC / 32; kb2++) {
                const uint32_t kloc = (uint32_t)kb2 * 64;
                uint32_t ahA[4], ahB[4], alA[4], alB[4];
                ldsm_x4(ahA, a_hi_base + a_row_off + kloc);
                ldsm_x4(ahB, a_hi_base + a_row_off + kloc + 32);
                ldsm_x4(alA, a_lo_base + a_row_off + kloc);
                ldsm_x4(alB, a_lo_base + a_row_off + kloc + 32);

                uint32_t bh[4], bl[4];
                ldsm_x4(bh, sbase + OFF_BHI + b_lm + kB_chunk + kloc);
                ldsm_x4(bl, sbase + OFF_BLO + b_lm + kB_chunk + kloc);

                mma_bf16(d0, ahA, bh[0], bh[1]);
                mma_bf16(d1, ahB, bh[2], bh[3]);
                mma_bf16(d0, ahA, bl[0], bl[1]);
                mma_bf16(d1, ahB, bl[2], bl[3]);
                mma_bf16(d0, alA, bh[0], bh[1]);
                mma_bf16(d1, alB, bh[2], bh[3]);
            }
        }

        float4 dq;
        dq.x = d0[0] + d1[0]; dq.y = d0[1] + d1[1];
        dq.z = d0[2] + d1[2]; dq.w = d0[3] + d1[3];
        redbuf[w_self * 32 + lane] = dq;
        __syncthreads();

        if (gate_owner) {
            float4 dh1 = redbuf[w_h1 * 32 + lane];
            float4 dz0 = redbuf[w_z0 * 32 + lane];
            float4 dz1 = redbuf[w_z1 * 32 + lane];
            float dh[4] = { dq.x + dh1.x, dq.y + dh1.y, dq.z + dh1.z, dq.w + dh1.w };
            float dz[4] = { dz0.x + dz1.x, dz0.y + dz1.y, dz0.z + dz1.z, dz0.w + dz1.w };

            unsigned short* dhi = g_h_hi[(t + 1) & 1];
            unsigned short* dlo = g_h_lo[(t + 1) & 1];
            #pragma unroll
            for (int qq = 0; qq < 2; qq++) {
                int br = (qq == 0) ? brow0 : brow1;
                float hn[2];
                #pragma unroll
                for (int cc = 0; cc < 2; cc++) {
                    float pre_h = dh[qq * 2 + cc] + xh[qq][cc];
                    float pre_z = dz[qq * 2 + cc] + xz[qq][cc];
                    float z  = 1.0f / (1.0f + expf(-pre_z));
                    float hb = fmaxf(pre_h, 0.0f);
                    hn[cc] = z * hold[qq][cc] + (1.0f - z) * hb;
                    hold[qq][cc] = hn[cc];
                }
                size_t o = (size_t)br * R_SZ + jg;
                *(uint32_t*)(dhi + o) = pack2_hi(hn[0], hn[1]);
                *(uint32_t*)(dlo + o) = pack2_lo(hn[0], hn[1]);
                if (t == T_SZ - 1) {
                    g_hf[o] = hn[0]; g_hf[o + 1] = hn[1];
                }
            }
        }

        // per-half grid barrier: 64 CTAs with same batch half (x & 1 == half)
        __threadfence();
        __syncthreads();
        if (tid == 0) flags[blockIdx.x * 32] = (unsigned)(t + 1);
        if (tid < 64) {
            while (flags[(tid * 2 + half) * 32] <= (unsigned)t) { }
        }
        __syncthreads();
    }
}

// ==================== Output: y = h_final @ Wy^T + by ====================
__global__ void __launch_bounds__(128) output_kernel(const float* __restrict__ Wy,
                                                     const float* __restrict__ by,
                                                     float* __restrict__ out) {
    __shared__ float shh[R_SZ];
    const int b = blockIdx.x;
    const int o = blockIdx.y * 128 + threadIdx.x;
    const float* hrow = g_hf + (size_t)b * R_SZ;
    #pragma unroll
    for (int v = 0; v < 2; v++) {
        int i4 = threadIdx.x + v * 128;
        ((float4*)shh)[i4] = *(const float4*)(hrow + i4 * 4);
    }
    __syncthreads();
    float acc = __ldg(&by[o]);
    const float* wrow = Wy + (size_t)o * R_SZ;
    #pragma unroll 8
    for (int k4 = 0; k4 < R_SZ / 4; k4++) {
        float4 h4 = ((const float4*)shh)[k4];
        float4 w4 = __ldg((const float4*)(wrow + k4 * 4));
        acc = fmaf(h4.x, w4.x, acc); acc = fmaf(h4.y, w4.y, acc);
        acc = fmaf(h4.z, w4.z, acc); acc = fmaf(h4.w, w4.w, acc);
    }
    out[(size_t)b * O_SZ + o] = acc;
}

// ==================== launch ====================
extern "C" void kernel_launch(void* const* d_in, const int* in_sizes, int n_in,
                              void* d_out, int out_size) {
    const float* x   = (const float*)d_in[0];
    const float* Wxh = (const float*)d_in[1];
    const float* bh  = (const float*)d_in[2];
    const float* Whh = (const float*)d_in[3];
    const float* Wxz = (const float*)d_in[4];
    const float* bz  = (const float*)d_in[5];
    const float* Whz = (const float*)d_in[6];
    const float* Wy  = (const float*)d_in[7];
    const float* by  = (const float*)d_in[8];
    float* out = (float*)d_out;

    static bool attr_set = false;
    if (!attr_set) {
        cudaFuncSetAttribute(scan_kernel,
                             cudaFuncAttributeMaxDynamicSharedMemorySize, SCAN_SMEM);
        cudaFuncSetAttribute(precompute_mma,
                             cudaFuncAttributeMaxDynamicSharedMemorySize, PP_SMEM);
        attr_set = true;
    }

    unsigned short *xhi_p, *xlo_p, *whi_p, *wlo_p;
    cudaGetSymbolAddress((void**)&xhi_p, g_x_hi);
    cudaGetSymbolAddress((void**)&xlo_p, g_x_lo);
    cudaGetSymbolAddress((void**)&whi_p, g_w_hi);
    cudaGetSymbolAddress((void**)&wlo_p, g_w_lo);
    split_kernel<<<(int)((size_t)M_SZ * D_SZ / 1024), 256>>>(x, xhi_p, xlo_p);
    split_kernel<<<(R_SZ * D_SZ) / 1024, 256>>>(Wxh, whi_p, wlo_p);
    split_kernel<<<(R_SZ * D_SZ) / 1024, 256>>>(Wxz, whi_p + (size_t)R_SZ * D_SZ,
                                                wlo_p + (size_t)R_SZ * D_SZ);

    precompute_mma<<<dim3(2048 / 128, M_SZ / 128), 512, PP_SMEM>>>(bh, bz);
    mz_kernel<<<dim3(R_SZ / 64, R_SZ / 64), 256>>>(Wxz, Whz);
    init_kernel<<<(B_SZ * R_SZ + 255) / 256, 256>>>();
    scan_kernel<<<NCTA, 512, SCAN_SMEM>>>(Whh);
    output_kernel<<<dim3(B_SZ, O_SZ / 128), 128>>>(Wy, by, out);
}